// round 7
// baseline (speedup 1.0000x reference)
#include <cuda_runtime.h>
#include <cuda_fp16.h>
#include <cstdint>

#define BB   2
#define CC   64
#define HH   256
#define WW   256
#define KK   9
#define ND   3
#define NOFF 54
#define TPX  128

typedef unsigned long long ull;
typedef unsigned int u32;

__device__ __forceinline__ u32 f2tf32(float f) {
    u32 r;
    asm("cvt.rna.tf32.f32 %0, %1;" : "=r"(r) : "f"(f));
    return r;
}

__device__ __forceinline__ void mma_tf32(float* c,
                                         u32 a0, u32 a1, u32 a2, u32 a3,
                                         u32 b0, u32 b1) {
    asm("mma.sync.aligned.m16n8k8.row.col.f32.tf32.tf32.f32 "
        "{%0,%1,%2,%3}, {%4,%5,%6,%7}, {%8,%9}, {%0,%1,%2,%3};"
        : "+f"(c[0]), "+f"(c[1]), "+f"(c[2]), "+f"(c[3])
        : "r"(a0), "r"(a1), "r"(a2), "r"(a3), "r"(b0), "r"(b1));
}

// ---------------- scratch ----------------------------------------------------
// g_xT: fp16, channel order = perm(c) = (c&3)*16 + (c>>2), NHWC
__device__ __half g_xT[(size_t)BB * HH * WW * CC];
__device__ float  g_offT[(size_t)BB * HH * NOFF * WW];
__device__ float  g_weffF[(size_t)ND * KK * CC * CC];   // fragment-ordered tf32
__device__ float  g_woffF[(size_t)KK * CC * CC];

// column position within sS row for original channel c:
// fp16 chunk f = perm(c)>>3, r = perm(c)&7; column = 4f + 32(r>>2) + (r&3)
__device__ __forceinline__ int pcol(int c) {
    int pos = (c & 3) * 16 + (c >> 2);
    int f = pos >> 3, r = pos & 7;
    return 4 * f + 32 * (r >> 2) + (r & 3);
}
// fragment index in a 64x64 tile from (oo, column c2)
__device__ __forceinline__ int frag_index(int oo, int c2) {
    int le = c2 >> 4, rem = c2 & 15, s2 = rem >> 2, el = rem & 3;
    int wn = oo >> 5, r5 = oo & 31, nt = r5 >> 3, lg = r5 & 7;
    return ((((wn * 4 + s2) * 4 + nt) * 8 + lg) * 4 + le) * 4 + el;
}

// ---------------- 1) transpose x -> permuted fp16 NHWC ------------------------
__global__ void transpose_kernel(const float* __restrict__ x) {
    __shared__ float tile[32][33];
    int bh = blockIdx.z;
    int b  = bh / HH, h = bh % HH;
    int w0 = blockIdx.x * 32;
    int c0 = blockIdx.y * 32;
    int tx = threadIdx.x, ty = threadIdx.y;

    #pragma unroll
    for (int j = 0; j < 4; j++) {
        int c = c0 + ty + j * 8;
        tile[ty + j * 8][tx] = x[(((size_t)b * CC + c) * HH + h) * WW + (w0 + tx)];
    }
    __syncthreads();
    #pragma unroll
    for (int j = 0; j < 4; j++) {
        int w = w0 + ty + j * 8;
        int c = c0 + tx;
        int pos = ((c & 3) << 4) | (c >> 2);
        g_xT[(((size_t)b * HH + h) * WW + w) * CC + pos] = __float2half(tile[tx][ty + j * 8]);
    }
}

// ---------------- 2a) Weff -> fragment-ordered tf32 ---------------------------
__global__ void weff_kernel(const float* __restrict__ Wd,
                            const float* __restrict__ Wfuse) {
    int idx = blockIdx.x * 256 + threadIdx.x;
    if (idx >= ND * KK * CC * CC) return;
    int oo = idx % CC;
    int c  = (idx / CC) % CC;
    int k  = (idx / (CC * CC)) % KK;
    int i  = idx / (CC * CC * KK);
    float acc = 0.f;
    #pragma unroll 8
    for (int o = 0; o < CC; o++) {
        acc = fmaf(Wfuse[oo * (ND * CC) + i * CC + o],
                   Wd[(((size_t)(i * CC + o) * CC + c) * KK) + k], acc);
    }
    int tap = i * KK + k;
    ((u32*)g_weffF)[(size_t)tap * CC * CC + frag_index(oo, pcol(c))] = f2tf32(acc);
}

// ---------------- 2b) Woff -> fragment-ordered tf32 ---------------------------
__global__ void woff_kernel(const float* __restrict__ Woff) {
    int idx = blockIdx.x * 256 + threadIdx.x;
    if (idx >= KK * CC * CC) return;
    int c  = idx % CC;
    int oc = (idx / CC) % CC;
    int k  = idx / (CC * CC);
    float v = (oc < NOFF) ? Woff[(size_t)oc * CC * KK + c * KK + k] : 0.f;
    ((u32*)g_woffF)[(size_t)k * CC * CC + frag_index(oc, pcol(c))] = f2tf32(v);
}

// ---------------- 3) offset conv via mma.sync (9 shifted GEMMs) ---------------
// smem: sX[2][130*64] u32 (66560B) ; row stride 64, XOR chunk swizzle
__global__ __launch_bounds__(256, 2)
void offconv_kernel(const float* __restrict__ boff) {
    extern __shared__ u32 smo[];
    u32* sX = smo;

    int bh = blockIdx.y;
    int b  = bh / HH, h = bh % HH;
    int w0 = blockIdx.x * TPX;
    int tid = threadIdx.x;
    int lane = tid & 31, wid = tid >> 5;
    int warp_m = wid >> 1;
    int warp_n = wid & 1;
    int lg = lane >> 2;
    int le = lane & 3;

    const __half* xTrow = g_xT + (size_t)b * HH * WW * CC;

    float acc[2][4][4];
    #pragma unroll
    for (int mt = 0; mt < 2; mt++)
        #pragma unroll
        for (int nt = 0; nt < 4; nt++)
            #pragma unroll
            for (int e = 0; e < 4; e++) acc[mt][nt][e] = 0.f;

    for (int ky = 0; ky < 3; ky++) {
        int row = h + ky - 1;
        if (row < 0 || row >= HH) continue;

        u32* sXp = sX + (ky & 1) * (130 * 64);
        {
            const uint4* src = (const uint4*)(xTrow + (size_t)row * WW * CC);
            for (int t = tid; t < 130 * 8; t += 256) {
                int px = t >> 3, ch = t & 7;
                int w = w0 - 1 + px;
                float ov[8];
                #pragma unroll
                for (int m = 0; m < 8; m++) ov[m] = 0.f;
                if (w >= 0 && w < WW) {
                    uint4 u = __ldg(src + (size_t)w * 8 + ch);
                    const __half2* hp = (const __half2*)&u;
                    #pragma unroll
                    for (int m = 0; m < 4; m++) {
                        float2 fv = __half22float2(hp[m]);
                        ov[2 * m]     = fv.x;
                        ov[2 * m + 1] = fv.y;
                    }
                }
                int s = px & 7;
                uint4 q0 = make_uint4(f2tf32(ov[0]), f2tf32(ov[1]), f2tf32(ov[2]), f2tf32(ov[3]));
                uint4 q1 = make_uint4(f2tf32(ov[4]), f2tf32(ov[5]), f2tf32(ov[6]), f2tf32(ov[7]));
                *(uint4*)&sXp[px * 64 + ((ch ^ s) * 4)]       = q0;
                *(uint4*)&sXp[px * 64 + (((ch + 8) ^ s) * 4)] = q1;
            }
        }
        __syncthreads();

        #pragma unroll
        for (int kx = 0; kx < 3; kx++) {
            int k = ky * 3 + kx;
            const float4* wF = (const float4*)g_woffF + (size_t)k * 1024 + warp_n * 512;
            int abase = warp_m * 32 + kx;
            int rs = (abase + lg) & 7;
            #pragma unroll
            for (int s2 = 0; s2 < 4; s2++) {
                int swz = ((le * 4 + s2) ^ rs) * 4;
                uint4 a0lo = *(const uint4*)&sXp[(abase + lg)      * 64 + swz];
                uint4 a0hi = *(const uint4*)&sXp[(abase + lg + 8)  * 64 + swz];
                uint4 a1lo = *(const uint4*)&sXp[(abase + lg + 16) * 64 + swz];
                uint4 a1hi = *(const uint4*)&sXp[(abase + lg + 24) * 64 + swz];
                #pragma unroll
                for (int nt = 0; nt < 4; nt++) {
                    float4 bvf = __ldg(wF + (s2 * 4 + nt) * 32 + lane);
                    u32 b0 = __float_as_uint(bvf.x), b1 = __float_as_uint(bvf.y);
                    u32 b2 = __float_as_uint(bvf.z), b3 = __float_as_uint(bvf.w);
                    mma_tf32(acc[0][nt], a0lo.x, a0hi.x, a0lo.y, a0hi.y, b0, b1);
                    mma_tf32(acc[0][nt], a0lo.z, a0hi.z, a0lo.w, a0hi.w, b2, b3);
                    mma_tf32(acc[1][nt], a1lo.x, a1hi.x, a1lo.y, a1hi.y, b0, b1);
                    mma_tf32(acc[1][nt], a1lo.z, a1hi.z, a1lo.w, a1hi.w, b2, b3);
                }
            }
        }
        __syncthreads();
    }

    // epilogue: frags(+bias) -> smem [oc][px] -> coalesced g_offT stores
    float* sOut = (float*)smo;
    __syncthreads();
    #pragma unroll
    for (int mt = 0; mt < 2; mt++) {
        int px0 = warp_m * 32 + mt * 16 + lg;
        #pragma unroll
        for (int nt = 0; nt < 4; nt++) {
            int oc = warp_n * 32 + nt * 8 + 2 * le;
            float b0 = (oc < NOFF)     ? __ldg(&boff[oc])     : 0.f;
            float b1 = (oc + 1 < NOFF) ? __ldg(&boff[oc + 1]) : 0.f;
            sOut[oc * TPX + px0]           = acc[mt][nt][0] + b0;
            sOut[(oc + 1) * TPX + px0]     = acc[mt][nt][1] + b1;
            sOut[oc * TPX + px0 + 8]       = acc[mt][nt][2] + b0;
            sOut[(oc + 1) * TPX + px0 + 8] = acc[mt][nt][3] + b1;
        }
    }
    __syncthreads();
    {
        int oc = tid >> 2;
        int f0 = tid & 3;
        if (oc < NOFF) {
            float4* op = (float4*)(g_offT + ((size_t)bh * NOFF + oc) * WW + w0);
            const float4* sp = (const float4*)(sOut + oc * TPX);
            #pragma unroll
            for (int j = 0; j < 8; j++) op[f0 + j * 4] = sp[f0 + j * 4];
        }
    }
}

// ---------------- 4) main: fp16 gather + swizzled smem + mma.sync tf32 -------
// smem floats: sS 128*64 (32768B) + sG 2*128*8 (8192B) = 40960B -> 3 CTAs/SM
#define SMF_S   0
#define SMF_G   (TPX * 64)
#define SMF_TOT (SMF_G + 2 * TPX * 8)

__global__ __launch_bounds__(256, 3)
void main_kernel(float* __restrict__ out) {
    extern __shared__ float sm[];
    u32*   sSu = (u32*)(sm + SMF_S);
    float* sG  = sm + SMF_G;

    int bh = blockIdx.y;
    int b  = bh / HH, h = bh % HH;
    int w0 = blockIdx.x * TPX;
    int tid = threadIdx.x;
    int lane = tid & 31, wid = tid >> 5;

    int grp4 = tid >> 3;          // 32 groups, 4 px each
    int f    = tid & 7;           // fp16 16B chunk within 128B row
    int warp_m = wid >> 1;
    int warp_n = wid & 1;
    int lg = lane >> 2;
    int le = lane & 3;

    const char*  xTb  = (const char*)(g_xT + (size_t)b * HH * WW * CC);
    const float* offb = g_offT + (size_t)bh * NOFF * WW + w0;

    float acc[2][4][4];
    #pragma unroll
    for (int mt = 0; mt < 2; mt++)
        #pragma unroll
        for (int nt = 0; nt < 4; nt++)
            #pragma unroll
            for (int e = 0; e < 4; e++) acc[mt][nt][e] = 0.f;

    auto setup = [&](int tap, int buf) {
        if (tid < TPX) {
            int px = tid;
            int i = tap / KK, k = tap - i * KK;
            int d = 1 << i;
            float dy = __ldg(offb + (size_t)(i * 18 + 2 * k) * WW + px);
            float dx = __ldg(offb + (size_t)(i * 18 + 2 * k + 1) * WW + px);
            float ys  = (float)h + (float)((k / 3 - 1) * d) + dy;
            float xsf = (float)(w0 + px) + (float)((k % 3 - 1) * d) + dx;
            float y0f = floorf(ys), x0f = floorf(xsf);
            float wy1 = ys - y0f, wx1 = xsf - x0f, wy0 = 1.f - wy1, wx0 = 1.f - wx1;
            float y1f = y0f + 1.f, x1f = x0f + 1.f;
            float vy0 = (y0f >= 0.f && y0f <= 255.f) ? 1.f : 0.f;
            float vy1 = (y1f >= 0.f && y1f <= 255.f) ? 1.f : 0.f;
            float vx0 = (x0f >= 0.f && x0f <= 255.f) ? 1.f : 0.f;
            float vx1 = (x1f >= 0.f && x1f <= 255.f) ? 1.f : 0.f;
            u32 iy0 = (u32)(int)fminf(fmaxf(y0f, 0.f), 255.f);
            u32 iy1 = (u32)(int)fminf(fmaxf(y1f, 0.f), 255.f);
            u32 ix0 = (u32)(int)fminf(fmaxf(x0f, 0.f), 255.f);
            u32 ix1 = (u32)(int)fminf(fmaxf(x1f, 0.f), 255.f);
            uint4 o;
            o.x = ((iy0 * WW + ix0) * CC) * 2u;   // byte offsets (fp16)
            o.y = ((iy0 * WW + ix1) * CC) * 2u;
            o.z = ((iy1 * WW + ix0) * CC) * 2u;
            o.w = ((iy1 * WW + ix1) * CC) * 2u;
            float4 cw = make_float4(wy0 * wx0 * vy0 * vx0, wy0 * wx1 * vy0 * vx1,
                                    wy1 * wx0 * vy1 * vx0, wy1 * wx1 * vy1 * vx1);
            *(uint4*) &sG[(buf * TPX + px) * 8]     = o;
            *(float4*)&sG[(buf * TPX + px) * 8 + 4] = cw;
        }
    };

    setup(0, 0);
    __syncthreads();

    for (int tap = 0; tap < ND * KK; tap++) {
        int p = tap & 1;

        // gather: 4 px per group of 8 lanes; each lane one 16B fp16 chunk/corner
        #pragma unroll
        for (int j = 0; j < 4; j++) {
            int px = grp4 * 4 + j;
            const float* gp = &sG[(p * TPX + px) * 8];
            uint4  o  = *(const uint4*) (gp);
            float4 cw = *(const float4*)(gp + 4);
            uint4 u0 = __ldg((const uint4*)(xTb + o.x) + f);
            uint4 u1 = __ldg((const uint4*)(xTb + o.y) + f);
            uint4 u2 = __ldg((const uint4*)(xTb + o.z) + f);
            uint4 u3 = __ldg((const uint4*)(xTb + o.w) + f);
            const __half2* h0 = (const __half2*)&u0;
            const __half2* h1 = (const __half2*)&u1;
            const __half2* h2 = (const __half2*)&u2;
            const __half2* h3 = (const __half2*)&u3;
            float ov[8];
            #pragma unroll
            for (int m = 0; m < 4; m++) {
                float2 a  = __half22float2(h0[m]);
                float2 bb = __half22float2(h1[m]);
                float2 cc = __half22float2(h2[m]);
                float2 dd = __half22float2(h3[m]);
                ov[2 * m]     = cw.x * a.x + cw.y * bb.x + cw.z * cc.x + cw.w * dd.x;
                ov[2 * m + 1] = cw.x * a.y + cw.y * bb.y + cw.z * cc.y + cw.w * dd.y;
            }
            int s = px & 7;
            uint4 q0 = make_uint4(f2tf32(ov[0]), f2tf32(ov[1]), f2tf32(ov[2]), f2tf32(ov[3]));
            uint4 q1 = make_uint4(f2tf32(ov[4]), f2tf32(ov[5]), f2tf32(ov[6]), f2tf32(ov[7]));
            *(uint4*)&sSu[px * 64 + ((f ^ s) * 4)]       = q0;
            *(uint4*)&sSu[px * 64 + (((f + 8) ^ s) * 4)] = q1;
        }

        if (tap + 1 < ND * KK) setup(tap + 1, 1 - p);

        __syncthreads();

        // einsum: A from swizzled smem, B from fragment-ordered global
        {
            const float4* wF = (const float4*)g_weffF + (size_t)tap * 1024 + warp_n * 512;
            int arow = warp_m * 32 + lg;     // arow & 7 == lg
            #pragma unroll
            for (int s2 = 0; s2 < 4; s2++) {
                int swz = ((le * 4 + s2) ^ lg) * 4;
                uint4 a0lo = *(const uint4*)&sSu[(arow)      * 64 + swz];
                uint4 a0hi = *(const uint4*)&sSu[(arow + 8)  * 64 + swz];
                uint4 a1lo = *(const uint4*)&sSu[(arow + 16) * 64 + swz];
                uint4 a1hi = *(const uint4*)&sSu[(arow + 24) * 64 + swz];
                #pragma unroll
                for (int nt = 0; nt < 4; nt++) {
                    float4 bvf = __ldg(wF + (s2 * 4 + nt) * 32 + lane);
                    u32 b0 = __float_as_uint(bvf.x), b1 = __float_as_uint(bvf.y);
                    u32 b2 = __float_as_uint(bvf.z), b3 = __float_as_uint(bvf.w);
                    mma_tf32(acc[0][nt], a0lo.x, a0hi.x, a0lo.y, a0hi.y, b0, b1);
                    mma_tf32(acc[0][nt], a0lo.z, a0hi.z, a0lo.w, a0hi.w, b2, b3);
                    mma_tf32(acc[1][nt], a1lo.x, a1hi.x, a1lo.y, a1hi.y, b0, b1);
                    mma_tf32(acc[1][nt], a1lo.z, a1hi.z, a1lo.w, a1hi.w, b2, b3);
                }
            }
        }

        __syncthreads();
    }

    // epilogue: frags -> smem [oo][px] -> coalesced stores
    float* sOut = sm;
    #pragma unroll
    for (int mt = 0; mt < 2; mt++) {
        int px0 = warp_m * 32 + mt * 16 + lg;
        #pragma unroll
        for (int nt = 0; nt < 4; nt++) {
            int oo = warp_n * 32 + nt * 8 + 2 * le;
            sOut[oo * TPX + px0]           = acc[mt][nt][0];
            sOut[(oo + 1) * TPX + px0]     = acc[mt][nt][1];
            sOut[oo * TPX + px0 + 8]       = acc[mt][nt][2];
            sOut[(oo + 1) * TPX + px0 + 8] = acc[mt][nt][3];
        }
    }
    __syncthreads();
    {
        int row = tid >> 2;
        int f0  = tid & 3;
        float4* op = (float4*)(out + (((size_t)(b * CC + row) * HH + h) * WW + w0));
        const float4* sp = (const float4*)(sOut + row * TPX);
        #pragma unroll
        for (int j = 0; j < 8; j++) op[f0 + j * 4] = sp[f0 + j * 4];
    }
}

// ---------------- launch ------------------------------------------------------
extern "C" void kernel_launch(void* const* d_in, const int* in_sizes, int n_in,
                              void* d_out, int out_size) {
    const float* x     = (const float*)d_in[0];
    const float* Woff  = (const float*)d_in[1];
    const float* boff  = (const float*)d_in[2];
    const float* Wd    = (const float*)d_in[3];
    const float* Wfuse = (const float*)d_in[4];
    float* out = (float*)d_out;

    int smem_main = SMF_TOT * 4;          // 40960
    int smem_off  = 2 * 130 * 64 * 4;     // 66560
    static int smem_set = 0;
    if (!smem_set) {
        cudaFuncSetAttribute(main_kernel,
                             cudaFuncAttributeMaxDynamicSharedMemorySize, smem_main);
        cudaFuncSetAttribute(offconv_kernel,
                             cudaFuncAttributeMaxDynamicSharedMemorySize, smem_off);
        smem_set = 1;
    }

    transpose_kernel<<<dim3(WW / 32, CC / 32, BB * HH), dim3(32, 8)>>>(x);
    weff_kernel<<<(ND * KK * CC * CC + 255) / 256, 256>>>(Wd, Wfuse);
    woff_kernel<<<(KK * CC * CC + 255) / 256, 256>>>(Woff);
    offconv_kernel<<<dim3(WW / TPX, BB * HH), 256, smem_off>>>(boff);
    main_kernel<<<dim3(WW / TPX, BB * HH), 256, smem_main>>>(out);
}

// round 8
// speedup vs baseline: 1.1984x; 1.1984x over previous
#include <cuda_runtime.h>
#include <cstdint>

#define BB   2
#define CC   64
#define HH   256
#define WW   256
#define KK   9
#define ND   3
#define NOFF 54
#define TPX  128         // pixels per main-kernel block
#define SSTR 68          // padded float stride of sS rows
#define OSTR 68          // padded float stride of offconv sX rows

typedef unsigned long long ull;
typedef unsigned int u32;

__device__ __forceinline__ u32 f2tf32(float f) {
    u32 r;
    asm("cvt.rna.tf32.f32 %0, %1;" : "=r"(r) : "f"(f));
    return r;
}

// m16n8k8 tf32 mma (sm_80 baseline PTX -> HMMA on sm_103)
__device__ __forceinline__ void mma_tf32(float* c,
                                         u32 a0, u32 a1, u32 a2, u32 a3,
                                         u32 b0, u32 b1) {
    asm("mma.sync.aligned.m16n8k8.row.col.f32.tf32.tf32.f32 "
        "{%0,%1,%2,%3}, {%4,%5,%6,%7}, {%8,%9}, {%0,%1,%2,%3};"
        : "+f"(c[0]), "+f"(c[1]), "+f"(c[2]), "+f"(c[3])
        : "r"(a0), "r"(a1), "r"(a2), "r"(a3), "r"(b0), "r"(b1));
}

// ---------------- scratch ----------------------------------------------------
// g_xT: channel-PERMUTED NHWC fp32: position p holds channel c, perm(c)=(c&3)*16+(c>>2)
__device__ float g_xT[(size_t)BB * HH * WW * CC];
__device__ float g_offT[(size_t)BB * HH * NOFF * WW];   // offsets (bh, ch, w)
__device__ float g_weffF[(size_t)ND * KK * CC * CC];    // fragment-ordered tf32
__device__ float g_woffF[(size_t)KK * CC * CC];         // offset-conv weights (oc pad 64)

__device__ __forceinline__ int frag_index(int oo, int p) {
    int le = p >> 4, rem = p & 15, s2 = rem >> 2, el = rem & 3;
    int wn = oo >> 5, r5 = oo & 31, nt = r5 >> 3, lg = r5 & 7;
    return ((((wn * 4 + s2) * 4 + nt) * 8 + lg) * 4 + le) * 4 + el;
}

// ---------------- 1) transpose x -> permuted NHWC -----------------------------
__global__ void transpose_kernel(const float* __restrict__ x) {
    __shared__ float tile[32][33];
    int bh = blockIdx.z;
    int b  = bh / HH, h = bh % HH;
    int w0 = blockIdx.x * 32;
    int c0 = blockIdx.y * 32;
    int tx = threadIdx.x, ty = threadIdx.y;

    #pragma unroll
    for (int j = 0; j < 4; j++) {
        int c = c0 + ty + j * 8;
        tile[ty + j * 8][tx] = x[(((size_t)b * CC + c) * HH + h) * WW + (w0 + tx)];
    }
    __syncthreads();
    #pragma unroll
    for (int j = 0; j < 4; j++) {
        int w = w0 + ty + j * 8;
        int c = c0 + tx;
        int pos = ((c & 3) << 4) | (c >> 2);
        g_xT[(((size_t)b * HH + h) * WW + w) * CC + pos] = tile[tx][ty + j * 8];
    }
}

// ---------------- 2a) Weff -> fragment-ordered tf32 ---------------------------
__global__ void weff_kernel(const float* __restrict__ Wd,
                            const float* __restrict__ Wfuse) {
    int idx = blockIdx.x * 256 + threadIdx.x;
    if (idx >= ND * KK * CC * CC) return;
    int oo = idx % CC;
    int c  = (idx / CC) % CC;
    int k  = (idx / (CC * CC)) % KK;
    int i  = idx / (CC * CC * KK);
    float acc = 0.f;
    #pragma unroll 8
    for (int o = 0; o < CC; o++) {
        acc = fmaf(Wfuse[oo * (ND * CC) + i * CC + o],
                   Wd[(((size_t)(i * CC + o) * CC + c) * KK) + k], acc);
    }
    int tap = i * KK + k;
    int p = (c & 3) * 16 + (c >> 2);
    ((u32*)g_weffF)[(size_t)tap * CC * CC + frag_index(oo, p)] = f2tf32(acc);
}

// ---------------- 2b) Woff -> fragment-ordered tf32 (oc padded to 64) ---------
__global__ void woff_kernel(const float* __restrict__ Woff) {
    int idx = blockIdx.x * 256 + threadIdx.x;
    if (idx >= KK * CC * CC) return;
    int c  = idx % CC;
    int oc = (idx / CC) % CC;
    int k  = idx / (CC * CC);
    float v = (oc < NOFF) ? Woff[(size_t)oc * CC * KK + c * KK + k] : 0.f;
    int p = (c & 3) * 16 + (c >> 2);
    ((u32*)g_woffF)[(size_t)k * CC * CC + frag_index(oc, p)] = f2tf32(v);
}

// ---------------- 3) offset conv via mma.sync (9 shifted GEMMs) ---------------
__global__ __launch_bounds__(256, 2)
void offconv_kernel(const float* __restrict__ boff) {
    extern __shared__ u32 smo[];
    u32* sX = smo;                        // 2 * 130 * OSTR

    int bh = blockIdx.y;
    int b  = bh / HH, h = bh % HH;
    int w0 = blockIdx.x * TPX;
    int tid = threadIdx.x;
    int lane = tid & 31, wid = tid >> 5;
    int warp_m = wid >> 1;
    int warp_n = wid & 1;
    int lg = lane >> 2;
    int le = lane & 3;

    const float* xTrow = g_xT + (size_t)b * HH * WW * CC;

    float acc[2][4][4];
    #pragma unroll
    for (int mt = 0; mt < 2; mt++)
        #pragma unroll
        for (int nt = 0; nt < 4; nt++)
            #pragma unroll
            for (int e = 0; e < 4; e++) acc[mt][nt][e] = 0.f;

    for (int ky = 0; ky < 3; ky++) {
        int row = h + ky - 1;
        if (row < 0 || row >= HH) continue;

        u32* sXp = sX + (ky & 1) * (130 * OSTR);
        {
            const float4* src = (const float4*)(xTrow + (size_t)row * WW * CC);
            for (int t = tid; t < 130 * 16; t += 256) {
                int px = t >> 4, ch = t & 15;
                int w = w0 - 1 + px;
                uint4 val = make_uint4(0u, 0u, 0u, 0u);
                if (w >= 0 && w < WW) {
                    float4 v = __ldg(src + (size_t)w * 16 + ch);
                    val.x = f2tf32(v.x); val.y = f2tf32(v.y);
                    val.z = f2tf32(v.z); val.w = f2tf32(v.w);
                }
                *(uint4*)&sXp[px * OSTR + ch * 4] = val;
            }
        }
        __syncthreads();

        #pragma unroll
        for (int kx = 0; kx < 3; kx++) {
            int k = ky * 3 + kx;
            const float4* wF = (const float4*)g_woffF + (size_t)k * 1024 + warp_n * 512;
            int abase = warp_m * 32 + kx;
            #pragma unroll
            for (int s2 = 0; s2 < 4; s2++) {
                int cofs = le * 16 + 4 * s2;
                uint4 a0lo = *(const uint4*)&sXp[(abase + lg)      * OSTR + cofs];
                uint4 a0hi = *(const uint4*)&sXp[(abase + lg + 8)  * OSTR + cofs];
                uint4 a1lo = *(const uint4*)&sXp[(abase + lg + 16) * OSTR + cofs];
                uint4 a1hi = *(const uint4*)&sXp[(abase + lg + 24) * OSTR + cofs];
                #pragma unroll
                for (int nt = 0; nt < 4; nt++) {
                    float4 bvf = __ldg(wF + (s2 * 4 + nt) * 32 + lane);
                    u32 b0 = __float_as_uint(bvf.x), b1 = __float_as_uint(bvf.y);
                    u32 b2 = __float_as_uint(bvf.z), b3 = __float_as_uint(bvf.w);
                    mma_tf32(acc[0][nt], a0lo.x, a0hi.x, a0lo.y, a0hi.y, b0, b1);
                    mma_tf32(acc[0][nt], a0lo.z, a0hi.z, a0lo.w, a0hi.w, b2, b3);
                    mma_tf32(acc[1][nt], a1lo.x, a1hi.x, a1lo.y, a1hi.y, b0, b1);
                    mma_tf32(acc[1][nt], a1lo.z, a1hi.z, a1lo.w, a1hi.w, b2, b3);
                }
            }
        }
        __syncthreads();
    }

    // epilogue: frags(+bias) -> smem [oc][px] -> coalesced g_offT stores
    float* sOut = (float*)smo;
    __syncthreads();
    #pragma unroll
    for (int mt = 0; mt < 2; mt++) {
        int px0 = warp_m * 32 + mt * 16 + lg;
        #pragma unroll
        for (int nt = 0; nt < 4; nt++) {
            int oc = warp_n * 32 + nt * 8 + 2 * le;
            float b0 = (oc < NOFF)     ? __ldg(&boff[oc])     : 0.f;
            float b1 = (oc + 1 < NOFF) ? __ldg(&boff[oc + 1]) : 0.f;
            sOut[oc * TPX + px0]           = acc[mt][nt][0] + b0;
            sOut[(oc + 1) * TPX + px0]     = acc[mt][nt][1] + b1;
            sOut[oc * TPX + px0 + 8]       = acc[mt][nt][2] + b0;
            sOut[(oc + 1) * TPX + px0 + 8] = acc[mt][nt][3] + b1;
        }
    }
    __syncthreads();
    {
        int oc = tid >> 2;
        int f0 = tid & 3;
        if (oc < NOFF) {
            float4* op = (float4*)(g_offT + ((size_t)bh * NOFF + oc) * WW + w0);
            const float4* sp = (const float4*)(sOut + oc * TPX);
            #pragma unroll
            for (int j = 0; j < 8; j++) op[f0 + j * 4] = sp[f0 + j * 4];
        }
    }
}

// ---------------- 4) main: gather + mma.sync, DOUBLE-BUFFERED sS, 1 sync/tap --
// smem floats: sS 2*128*68 (69632B), sG 2*128*8 (8192B) = 77824B -> 2 CTAs/SM
#define SMF_S   0
#define SMF_G   (2 * TPX * SSTR)
#define SMF_TOT (SMF_G + 2 * TPX * 8)

__global__ __launch_bounds__(256, 2)
void main_kernel(float* __restrict__ out) {
    extern __shared__ float sm[];
    float* sG = sm + SMF_G;

    int bh = blockIdx.y;
    int b  = bh / HH, h = bh % HH;
    int w0 = blockIdx.x * TPX;
    int tid = threadIdx.x;
    int lane = tid & 31, wid = tid >> 5;

    int grp = tid >> 4;           // gather group 0..15 (8 px each)
    int f   = tid & 15;           // 16B chunk lane
    int warp_m = wid >> 1;
    int warp_n = wid & 1;
    int lg = lane >> 2;
    int le = lane & 3;

    const char*  xTb  = (const char*)(g_xT + (size_t)b * HH * WW * CC);
    const float* offb = g_offT + (size_t)bh * NOFF * WW + w0;

    float acc[2][4][4];
    #pragma unroll
    for (int mt = 0; mt < 2; mt++)
        #pragma unroll
        for (int nt = 0; nt < 4; nt++)
            #pragma unroll
            for (int e = 0; e < 4; e++) acc[mt][nt][e] = 0.f;

    auto setup = [&](int tap, int buf) {
        if (tid < TPX) {
            int px = tid;
            int i = tap / KK, k = tap - i * KK;
            int d = 1 << i;
            float dy = __ldg(offb + (size_t)(i * 18 + 2 * k) * WW + px);
            float dx = __ldg(offb + (size_t)(i * 18 + 2 * k + 1) * WW + px);
            float ys  = (float)h + (float)((k / 3 - 1) * d) + dy;
            float xsf = (float)(w0 + px) + (float)((k % 3 - 1) * d) + dx;
            float y0f = floorf(ys), x0f = floorf(xsf);
            float wy1 = ys - y0f, wx1 = xsf - x0f, wy0 = 1.f - wy1, wx0 = 1.f - wx1;
            float y1f = y0f + 1.f, x1f = x0f + 1.f;
            float vy0 = (y0f >= 0.f && y0f <= 255.f) ? 1.f : 0.f;
            float vy1 = (y1f >= 0.f && y1f <= 255.f) ? 1.f : 0.f;
            float vx0 = (x0f >= 0.f && x0f <= 255.f) ? 1.f : 0.f;
            float vx1 = (x1f >= 0.f && x1f <= 255.f) ? 1.f : 0.f;
            u32 iy0 = (u32)(int)fminf(fmaxf(y0f, 0.f), 255.f);
            u32 iy1 = (u32)(int)fminf(fmaxf(y1f, 0.f), 255.f);
            u32 ix0 = (u32)(int)fminf(fmaxf(x0f, 0.f), 255.f);
            u32 ix1 = (u32)(int)fminf(fmaxf(x1f, 0.f), 255.f);
            uint4 o;
            o.x = ((iy0 * WW + ix0) * CC) * 4u;
            o.y = ((iy0 * WW + ix1) * CC) * 4u;
            o.z = ((iy1 * WW + ix0) * CC) * 4u;
            o.w = ((iy1 * WW + ix1) * CC) * 4u;
            float4 cw = make_float4(wy0 * wx0 * vy0 * vx0, wy0 * wx1 * vy0 * vx1,
                                    wy1 * wx0 * vy1 * vx0, wy1 * wx1 * vy1 * vx1);
            *(uint4*) &sG[(buf * TPX + px) * 8]     = o;
            *(float4*)&sG[(buf * TPX + px) * 8 + 4] = cw;
        }
    };

    setup(0, 0);
    __syncthreads();

    for (int tap = 0; tap < ND * KK; tap++) {
        int p = tap & 1;
        u32* sSu = (u32*)(sm + SMF_S + p * (TPX * SSTR));

        // gather tap -> sS[p]; mma(tap-1) may still be reading sS[1-p]: no hazard
        {
            const float* gp = &sG[(p * TPX + grp * 8) * 8];
            uint4  o  = *(const uint4*) (gp);
            float4 cw = *(const float4*)(gp + 4);
            float4 c0 = __ldg((const float4*)(xTb + o.x) + f);
            float4 c1 = __ldg((const float4*)(xTb + o.y) + f);
            float4 c2 = __ldg((const float4*)(xTb + o.z) + f);
            float4 c3 = __ldg((const float4*)(xTb + o.w) + f);

            #pragma unroll
            for (int j = 0; j < 8; j++) {
                uint4 no; float4 ncw;
                float4 n0, n1, n2, n3;
                if (j < 7) {
                    const float* gq = &sG[(p * TPX + grp * 8 + j + 1) * 8];
                    no  = *(const uint4*) (gq);
                    ncw = *(const float4*)(gq + 4);
                    n0 = __ldg((const float4*)(xTb + no.x) + f);
                    n1 = __ldg((const float4*)(xTb + no.y) + f);
                    n2 = __ldg((const float4*)(xTb + no.z) + f);
                    n3 = __ldg((const float4*)(xTb + no.w) + f);
                }
                uint4 r;
                r.x = f2tf32(cw.x*c0.x + cw.y*c1.x + cw.z*c2.x + cw.w*c3.x);
                r.y = f2tf32(cw.x*c0.y + cw.y*c1.y + cw.z*c2.y + cw.w*c3.y);
                r.z = f2tf32(cw.x*c0.z + cw.y*c1.z + cw.z*c2.z + cw.w*c3.z);
                r.w = f2tf32(cw.x*c0.w + cw.y*c1.w + cw.z*c2.w + cw.w*c3.w);
                *(uint4*)&sSu[(grp * 8 + j) * SSTR + 4 * f] = r;
                if (j < 7) { o = no; cw = ncw; c0 = n0; c1 = n1; c2 = n2; c3 = n3; }
            }
        }

        // stage next tap's bilinear setup into sG[1-p]
        if (tap + 1 < ND * KK) setup(tap + 1, 1 - p);

        __syncthreads();   // sS[p] + sG[1-p] visible; ONLY sync this tap

        // einsum: A from sS[p], B direct from fragment-ordered global (L1-hit)
        {
            const float4* wF = (const float4*)g_weffF + (size_t)tap * 1024 + warp_n * 512;
            int arow = warp_m * 32 + lg;
            #pragma unroll
            for (int s2 = 0; s2 < 4; s2++) {
                int cofs = le * 16 + 4 * s2;
                uint4 a0lo = *(const uint4*)&sSu[(arow)      * SSTR + cofs];
                uint4 a0hi = *(const uint4*)&sSu[(arow + 8)  * SSTR + cofs];
                uint4 a1lo = *(const uint4*)&sSu[(arow + 16) * SSTR + cofs];
                uint4 a1hi = *(const uint4*)&sSu[(arow + 24) * SSTR + cofs];
                #pragma unroll
                for (int nt = 0; nt < 4; nt++) {
                    float4 bvf = __ldg(wF + (s2 * 4 + nt) * 32 + lane);
                    u32 b0 = __float_as_uint(bvf.x), b1 = __float_as_uint(bvf.y);
                    u32 b2 = __float_as_uint(bvf.z), b3 = __float_as_uint(bvf.w);
                    mma_tf32(acc[0][nt], a0lo.x, a0hi.x, a0lo.y, a0hi.y, b0, b1);
                    mma_tf32(acc[0][nt], a0lo.z, a0hi.z, a0lo.w, a0hi.w, b2, b3);
                    mma_tf32(acc[1][nt], a1lo.x, a1hi.x, a1lo.y, a1hi.y, b0, b1);
                    mma_tf32(acc[1][nt], a1lo.z, a1hi.z, a1lo.w, a1hi.w, b2, b3);
                }
            }
        }
        // no trailing sync: next gather targets the other sS buffer
    }

    // epilogue: frags -> smem [oo][px] -> coalesced stores
    __syncthreads();   // all mma reads done before sOut overwrites sS[0]
    float* sOut = sm;
    #pragma unroll
    for (int mt = 0; mt < 2; mt++) {
        int px0 = warp_m * 32 + mt * 16 + lg;
        #pragma unroll
        for (int nt = 0; nt < 4; nt++) {
            int oo = warp_n * 32 + nt * 8 + 2 * le;
            sOut[oo * TPX + px0]           = acc[mt][nt][0];
            sOut[(oo + 1) * TPX + px0]     = acc[mt][nt][1];
            sOut[oo * TPX + px0 + 8]       = acc[mt][nt][2];
            sOut[(oo + 1) * TPX + px0 + 8] = acc[mt][nt][3];
        }
    }
    __syncthreads();
    {
        int row = tid >> 2;
        int f0  = tid & 3;
        float4* op = (float4*)(out + (((size_t)(b * CC + row) * HH + h) * WW + w0));
        const float4* sp = (const float4*)(sOut + row * TPX);
        #pragma unroll
        for (int j = 0; j < 8; j++) op[f0 + j * 4] = sp[f0 + j * 4];
    }
}

// ---------------- launch ------------------------------------------------------
extern "C" void kernel_launch(void* const* d_in, const int* in_sizes, int n_in,
                              void* d_out, int out_size) {
    const float* x     = (const float*)d_in[0];
    const float* Woff  = (const float*)d_in[1];
    const float* boff  = (const float*)d_in[2];
    const float* Wd    = (const float*)d_in[3];
    const float* Wfuse = (const float*)d_in[4];
    float* out = (float*)d_out;

    int smem_main = SMF_TOT * 4;          // 77824
    int smem_off  = 2 * 130 * OSTR * 4;
    static int smem_set = 0;
    if (!smem_set) {
        cudaFuncSetAttribute(main_kernel,
                             cudaFuncAttributeMaxDynamicSharedMemorySize, smem_main);
        cudaFuncSetAttribute(offconv_kernel,
                             cudaFuncAttributeMaxDynamicSharedMemorySize, smem_off);
        smem_set = 1;
    }

    transpose_kernel<<<dim3(WW / 32, CC / 32, BB * HH), dim3(32, 8)>>>(x);
    weff_kernel<<<(ND * KK * CC * CC + 255) / 256, 256>>>(Wd, Wfuse);
    woff_kernel<<<(KK * CC * CC + 255) / 256, 256>>>(Woff);
    offconv_kernel<<<dim3(WW / TPX, BB * HH), 256, smem_off>>>(boff);
    main_kernel<<<dim3(WW / TPX, BB * HH), 256, smem_main>>>(out);
}

// round 9
// speedup vs baseline: 1.2575x; 1.0493x over previous
#include <cuda_runtime.h>
#include <cuda_fp16.h>
#include <cstdint>

#define BB   2
#define CC   64
#define HH   256
#define WW   256
#define KK   9
#define ND   3
#define NOFF 54
#define TPX  128         // pixels per main-kernel block
#define SSTR 68          // padded float stride of sS rows
#define OSTR 68          // padded float stride of offconv sX rows

typedef unsigned long long ull;
typedef unsigned int u32;

__device__ __forceinline__ u32 f2tf32(float f) {
    u32 r;
    asm("cvt.rna.tf32.f32 %0, %1;" : "=r"(r) : "f"(f));
    return r;
}

// m16n8k8 tf32 mma (sm_80 baseline PTX -> HMMA on sm_103)
__device__ __forceinline__ void mma_tf32(float* c,
                                         u32 a0, u32 a1, u32 a2, u32 a3,
                                         u32 b0, u32 b1) {
    asm("mma.sync.aligned.m16n8k8.row.col.f32.tf32.tf32.f32 "
        "{%0,%1,%2,%3}, {%4,%5,%6,%7}, {%8,%9}, {%0,%1,%2,%3};"
        : "+f"(c[0]), "+f"(c[1]), "+f"(c[2]), "+f"(c[3])
        : "r"(a0), "r"(a1), "r"(a2), "r"(a3), "r"(b0), "r"(b1));
}

// ---------------- scratch ----------------------------------------------------
// g_xT: fp16, channel-PERMUTED NHWC: position p holds channel c, perm(c)=(c&3)*16+(c>>2)
__device__ __half g_xT[(size_t)BB * HH * WW * CC];
__device__ float  g_offT[(size_t)BB * HH * NOFF * WW];   // offsets (bh, ch, w)
__device__ float  g_weffF[(size_t)ND * KK * CC * CC];    // fragment-ordered tf32
__device__ float  g_woffF[(size_t)KK * CC * CC];         // offset-conv weights (oc pad 64)

__device__ __forceinline__ int frag_index(int oo, int p) {
    int le = p >> 4, rem = p & 15, s2 = rem >> 2, el = rem & 3;
    int wn = oo >> 5, r5 = oo & 31, nt = r5 >> 3, lg = r5 & 7;
    return ((((wn * 4 + s2) * 4 + nt) * 8 + lg) * 4 + le) * 4 + el;
}

// ---------------- 1) transpose x -> permuted fp16 NHWC ------------------------
__global__ void transpose_kernel(const float* __restrict__ x) {
    __shared__ float tile[32][33];
    int bh = blockIdx.z;
    int b  = bh / HH, h = bh % HH;
    int w0 = blockIdx.x * 32;
    int c0 = blockIdx.y * 32;
    int tx = threadIdx.x, ty = threadIdx.y;

    #pragma unroll
    for (int j = 0; j < 4; j++) {
        int c = c0 + ty + j * 8;
        tile[ty + j * 8][tx] = x[(((size_t)b * CC + c) * HH + h) * WW + (w0 + tx)];
    }
    __syncthreads();
    #pragma unroll
    for (int j = 0; j < 4; j++) {
        int w = w0 + ty + j * 8;
        int c = c0 + tx;
        int pos = ((c & 3) << 4) | (c >> 2);
        g_xT[(((size_t)b * HH + h) * WW + w) * CC + pos] = __float2half(tile[tx][ty + j * 8]);
    }
}

// ---------------- 2a) Weff -> fragment-ordered tf32 ---------------------------
__global__ void weff_kernel(const float* __restrict__ Wd,
                            const float* __restrict__ Wfuse) {
    int idx = blockIdx.x * 256 + threadIdx.x;
    if (idx >= ND * KK * CC * CC) return;
    int oo = idx % CC;
    int c  = (idx / CC) % CC;
    int k  = (idx / (CC * CC)) % KK;
    int i  = idx / (CC * CC * KK);
    float acc = 0.f;
    #pragma unroll 8
    for (int o = 0; o < CC; o++) {
        acc = fmaf(Wfuse[oo * (ND * CC) + i * CC + o],
                   Wd[(((size_t)(i * CC + o) * CC + c) * KK) + k], acc);
    }
    int tap = i * KK + k;
    int p = (c & 3) * 16 + (c >> 2);
    ((u32*)g_weffF)[(size_t)tap * CC * CC + frag_index(oo, p)] = f2tf32(acc);
}

// ---------------- 2b) Woff -> fragment-ordered tf32 (oc padded to 64) ---------
__global__ void woff_kernel(const float* __restrict__ Woff) {
    int idx = blockIdx.x * 256 + threadIdx.x;
    if (idx >= KK * CC * CC) return;
    int c  = idx % CC;
    int oc = (idx / CC) % CC;
    int k  = idx / (CC * CC);
    float v = (oc < NOFF) ? Woff[(size_t)oc * CC * KK + c * KK + k] : 0.f;
    int p = (c & 3) * 16 + (c >> 2);
    ((u32*)g_woffF)[(size_t)k * CC * CC + frag_index(oc, p)] = f2tf32(v);
}

// ---------------- 3) offset conv via mma.sync (9 shifted GEMMs) ---------------
__global__ __launch_bounds__(256, 2)
void offconv_kernel(const float* __restrict__ boff) {
    extern __shared__ u32 smo[];
    u32* sX = smo;                        // 2 * 130 * OSTR

    int bh = blockIdx.y;
    int b  = bh / HH, h = bh % HH;
    int w0 = blockIdx.x * TPX;
    int tid = threadIdx.x;
    int lane = tid & 31, wid = tid >> 5;
    int warp_m = wid >> 1;
    int warp_n = wid & 1;
    int lg = lane >> 2;
    int le = lane & 3;

    const __half* xTrow = g_xT + (size_t)b * HH * WW * CC;

    float acc[2][4][4];
    #pragma unroll
    for (int mt = 0; mt < 2; mt++)
        #pragma unroll
        for (int nt = 0; nt < 4; nt++)
            #pragma unroll
            for (int e = 0; e < 4; e++) acc[mt][nt][e] = 0.f;

    for (int ky = 0; ky < 3; ky++) {
        int row = h + ky - 1;
        if (row < 0 || row >= HH) continue;

        u32* sXp = sX + (ky & 1) * (130 * OSTR);
        {
            // stage 130 px, each row = 64 fp16 = 8 uint4 chunks
            const uint4* src = (const uint4*)(xTrow + (size_t)row * WW * CC);
            for (int t = tid; t < 130 * 8; t += 256) {
                int px = t >> 3, ch = t & 7;
                int w = w0 - 1 + px;
                u32 q[8];
                #pragma unroll
                for (int m = 0; m < 8; m++) q[m] = 0u;
                if (w >= 0 && w < WW) {
                    uint4 u = __ldg(src + (size_t)w * 8 + ch);
                    const __half2* hp = (const __half2*)&u;
                    #pragma unroll
                    for (int m = 0; m < 4; m++) {
                        float2 fv = __half22float2(hp[m]);
                        q[2 * m]     = f2tf32(fv.x);
                        q[2 * m + 1] = f2tf32(fv.y);
                    }
                }
                *(uint4*)&sXp[px * OSTR + ch * 8]     = make_uint4(q[0], q[1], q[2], q[3]);
                *(uint4*)&sXp[px * OSTR + ch * 8 + 4] = make_uint4(q[4], q[5], q[6], q[7]);
            }
        }
        __syncthreads();

        #pragma unroll
        for (int kx = 0; kx < 3; kx++) {
            int k = ky * 3 + kx;
            const float4* wF = (const float4*)g_woffF + (size_t)k * 1024 + warp_n * 512;
            int abase = warp_m * 32 + kx;
            #pragma unroll
            for (int s2 = 0; s2 < 4; s2++) {
                int cofs = le * 16 + 4 * s2;
                uint4 a0lo = *(const uint4*)&sXp[(abase + lg)      * OSTR + cofs];
                uint4 a0hi = *(const uint4*)&sXp[(abase + lg + 8)  * OSTR + cofs];
                uint4 a1lo = *(const uint4*)&sXp[(abase + lg + 16) * OSTR + cofs];
                uint4 a1hi = *(const uint4*)&sXp[(abase + lg + 24) * OSTR + cofs];
                #pragma unroll
                for (int nt = 0; nt < 4; nt++) {
                    float4 bvf = __ldg(wF + (s2 * 4 + nt) * 32 + lane);
                    u32 b0 = __float_as_uint(bvf.x), b1 = __float_as_uint(bvf.y);
                    u32 b2 = __float_as_uint(bvf.z), b3 = __float_as_uint(bvf.w);
                    mma_tf32(acc[0][nt], a0lo.x, a0hi.x, a0lo.y, a0hi.y, b0, b1);
                    mma_tf32(acc[0][nt], a0lo.z, a0hi.z, a0lo.w, a0hi.w, b2, b3);
                    mma_tf32(acc[1][nt], a1lo.x, a1hi.x, a1lo.y, a1hi.y, b0, b1);
                    mma_tf32(acc[1][nt], a1lo.z, a1hi.z, a1lo.w, a1hi.w, b2, b3);
                }
            }
        }
        __syncthreads();
    }

    // epilogue: frags(+bias) -> smem [oc][px] -> coalesced g_offT stores
    float* sOut = (float*)smo;
    __syncthreads();
    #pragma unroll
    for (int mt = 0; mt < 2; mt++) {
        int px0 = warp_m * 32 + mt * 16 + lg;
        #pragma unroll
        for (int nt = 0; nt < 4; nt++) {
            int oc = warp_n * 32 + nt * 8 + 2 * le;
            float b0 = (oc < NOFF)     ? __ldg(&boff[oc])     : 0.f;
            float b1 = (oc + 1 < NOFF) ? __ldg(&boff[oc + 1]) : 0.f;
            sOut[oc * TPX + px0]           = acc[mt][nt][0] + b0;
            sOut[(oc + 1) * TPX + px0]     = acc[mt][nt][1] + b1;
            sOut[oc * TPX + px0 + 8]       = acc[mt][nt][2] + b0;
            sOut[(oc + 1) * TPX + px0 + 8] = acc[mt][nt][3] + b1;
        }
    }
    __syncthreads();
    {
        int oc = tid >> 2;
        int f0 = tid & 3;
        if (oc < NOFF) {
            float4* op = (float4*)(g_offT + ((size_t)bh * NOFF + oc) * WW + w0);
            const float4* sp = (const float4*)(sOut + oc * TPX);
            #pragma unroll
            for (int j = 0; j < 8; j++) op[f0 + j * 4] = sp[f0 + j * 4];
        }
    }
}

// ---------------- 4) main: fp16 gather + mma.sync, double-buffered sS ---------
// smem floats: sS 2*128*68 (69632B), sG 2*128*8 (8192B) = 77824B -> 2 CTAs/SM
#define SMF_S   0
#define SMF_G   (2 * TPX * SSTR)
#define SMF_TOT (SMF_G + 2 * TPX * 8)

__global__ __launch_bounds__(256, 2)
void main_kernel(float* __restrict__ out) {
    extern __shared__ float sm[];
    float* sG = sm + SMF_G;

    int bh = blockIdx.y;
    int b  = bh / HH, h = bh % HH;
    int w0 = blockIdx.x * TPX;
    int tid = threadIdx.x;
    int lane = tid & 31, wid = tid >> 5;

    int grp = tid >> 4;           // gather group 0..15 (8 px each)
    int f   = tid & 15;           // 8B fp16 chunk lane (channels 4f..4f+3)
    int warp_m = wid >> 1;
    int warp_n = wid & 1;
    int lg = lane >> 2;
    int le = lane & 3;

    const char*  xTb  = (const char*)(g_xT + (size_t)b * HH * WW * CC);
    const float* offb = g_offT + (size_t)bh * NOFF * WW + w0;

    float acc[2][4][4];
    #pragma unroll
    for (int mt = 0; mt < 2; mt++)
        #pragma unroll
        for (int nt = 0; nt < 4; nt++)
            #pragma unroll
            for (int e = 0; e < 4; e++) acc[mt][nt][e] = 0.f;

    auto setup = [&](int tap, int buf) {
        if (tid < TPX) {
            int px = tid;
            int i = tap / KK, k = tap - i * KK;
            int d = 1 << i;
            float dy = __ldg(offb + (size_t)(i * 18 + 2 * k) * WW + px);
            float dx = __ldg(offb + (size_t)(i * 18 + 2 * k + 1) * WW + px);
            float ys  = (float)h + (float)((k / 3 - 1) * d) + dy;
            float xsf = (float)(w0 + px) + (float)((k % 3 - 1) * d) + dx;
            float y0f = floorf(ys), x0f = floorf(xsf);
            float wy1 = ys - y0f, wx1 = xsf - x0f, wy0 = 1.f - wy1, wx0 = 1.f - wx1;
            float y1f = y0f + 1.f, x1f = x0f + 1.f;
            float vy0 = (y0f >= 0.f && y0f <= 255.f) ? 1.f : 0.f;
            float vy1 = (y1f >= 0.f && y1f <= 255.f) ? 1.f : 0.f;
            float vx0 = (x0f >= 0.f && x0f <= 255.f) ? 1.f : 0.f;
            float vx1 = (x1f >= 0.f && x1f <= 255.f) ? 1.f : 0.f;
            u32 iy0 = (u32)(int)fminf(fmaxf(y0f, 0.f), 255.f);
            u32 iy1 = (u32)(int)fminf(fmaxf(y1f, 0.f), 255.f);
            u32 ix0 = (u32)(int)fminf(fmaxf(x0f, 0.f), 255.f);
            u32 ix1 = (u32)(int)fminf(fmaxf(x1f, 0.f), 255.f);
            uint4 o;
            o.x = ((iy0 * WW + ix0) * CC) * 2u;   // BYTE offsets (fp16)
            o.y = ((iy0 * WW + ix1) * CC) * 2u;
            o.z = ((iy1 * WW + ix0) * CC) * 2u;
            o.w = ((iy1 * WW + ix1) * CC) * 2u;
            float4 cw = make_float4(wy0 * wx0 * vy0 * vx0, wy0 * wx1 * vy0 * vx1,
                                    wy1 * wx0 * vy1 * vx0, wy1 * wx1 * vy1 * vx1);
            *(uint4*) &sG[(buf * TPX + px) * 8]     = o;
            *(float4*)&sG[(buf * TPX + px) * 8 + 4] = cw;
        }
    };

    setup(0, 0);
    __syncthreads();

    for (int tap = 0; tap < ND * KK; tap++) {
        int p = tap & 1;
        u32* sSu = (u32*)(sm + SMF_S + p * (TPX * SSTR));

        // gather tap -> sS[p]; same 8-deep pipeline as round 8, fp16 loads
        {
            const float* gp = &sG[(p * TPX + grp * 8) * 8];
            uint4  o  = *(const uint4*) (gp);
            float4 cw = *(const float4*)(gp + 4);
            uint2 c0 = __ldg((const uint2*)(xTb + o.x) + f);
            uint2 c1 = __ldg((const uint2*)(xTb + o.y) + f);
            uint2 c2 = __ldg((const uint2*)(xTb + o.z) + f);
            uint2 c3 = __ldg((const uint2*)(xTb + o.w) + f);

            #pragma unroll
            for (int j = 0; j < 8; j++) {
                uint4 no; float4 ncw;
                uint2 n0, n1, n2, n3;
                if (j < 7) {
                    const float* gq = &sG[(p * TPX + grp * 8 + j + 1) * 8];
                    no  = *(const uint4*) (gq);
                    ncw = *(const float4*)(gq + 4);
                    n0 = __ldg((const uint2*)(xTb + no.x) + f);
                    n1 = __ldg((const uint2*)(xTb + no.y) + f);
                    n2 = __ldg((const uint2*)(xTb + no.z) + f);
                    n3 = __ldg((const uint2*)(xTb + no.w) + f);
                }
                // 4 channels per lane: convert + combine
                float2 a0 = __half22float2(*(const __half2*)&c0.x);
                float2 a1 = __half22float2(*(const __half2*)&c0.y);
                float2 b0 = __half22float2(*(const __half2*)&c1.x);
                float2 b1 = __half22float2(*(const __half2*)&c1.y);
                float2 d0 = __half22float2(*(const __half2*)&c2.x);
                float2 d1 = __half22float2(*(const __half2*)&c2.y);
                float2 e0 = __half22float2(*(const __half2*)&c3.x);
                float2 e1 = __half22float2(*(const __half2*)&c3.y);
                uint4 r;
                r.x = f2tf32(cw.x*a0.x + cw.y*b0.x + cw.z*d0.x + cw.w*e0.x);
                r.y = f2tf32(cw.x*a0.y + cw.y*b0.y + cw.z*d0.y + cw.w*e0.y);
                r.z = f2tf32(cw.x*a1.x + cw.y*b1.x + cw.z*d1.x + cw.w*e1.x);
                r.w = f2tf32(cw.x*a1.y + cw.y*b1.y + cw.z*d1.y + cw.w*e1.y);
                *(uint4*)&sSu[(grp * 8 + j) * SSTR + 4 * f] = r;
                if (j < 7) { o = no; cw = ncw; c0 = n0; c1 = n1; c2 = n2; c3 = n3; }
            }
        }

        // stage next tap's bilinear setup into sG[1-p]
        if (tap + 1 < ND * KK) setup(tap + 1, 1 - p);

        __syncthreads();   // sS[p] + sG[1-p] visible; ONLY sync this tap

        // einsum: A from sS[p], B direct from fragment-ordered global (L1-hit)
        {
            const float4* wF = (const float4*)g_weffF + (size_t)tap * 1024 + warp_n * 512;
            int arow = warp_m * 32 + lg;
            #pragma unroll
            for (int s2 = 0; s2 < 4; s2++) {
                int cofs = le * 16 + 4 * s2;
                uint4 a0lo = *(const uint4*)&sSu[(arow)      * SSTR + cofs];
                uint4 a0hi = *(const uint4*)&sSu[(arow + 8)  * SSTR + cofs];
                uint4 a1lo = *(const uint4*)&sSu[(arow + 16) * SSTR + cofs];
                uint4 a1hi = *(const uint4*)&sSu[(arow + 24) * SSTR + cofs];
                #pragma unroll
                for (int nt = 0; nt < 4; nt++) {
                    float4 bvf = __ldg(wF + (s2 * 4 + nt) * 32 + lane);
                    u32 b0 = __float_as_uint(bvf.x), b1 = __float_as_uint(bvf.y);
                    u32 b2 = __float_as_uint(bvf.z), b3 = __float_as_uint(bvf.w);
                    mma_tf32(acc[0][nt], a0lo.x, a0hi.x, a0lo.y, a0hi.y, b0, b1);
                    mma_tf32(acc[0][nt], a0lo.z, a0hi.z, a0lo.w, a0hi.w, b2, b3);
                    mma_tf32(acc[1][nt], a1lo.x, a1hi.x, a1lo.y, a1hi.y, b0, b1);
                    mma_tf32(acc[1][nt], a1lo.z, a1hi.z, a1lo.w, a1hi.w, b2, b3);
                }
            }
        }
        // no trailing sync: next gather targets the other sS buffer
    }

    // epilogue: frags -> smem [oo][px] -> coalesced stores
    __syncthreads();
    float* sOut = sm;
    #pragma unroll
    for (int mt = 0; mt < 2; mt++) {
        int px0 = warp_m * 32 + mt * 16 + lg;
        #pragma unroll
        for (int nt = 0; nt < 4; nt++) {
            int oo = warp_n * 32 + nt * 8 + 2 * le;
            sOut[oo * TPX + px0]           = acc[mt][nt][0];
            sOut[(oo + 1) * TPX + px0]     = acc[mt][nt][1];
            sOut[oo * TPX + px0 + 8]       = acc[mt][nt][2];
            sOut[(oo + 1) * TPX + px0 + 8] = acc[mt][nt][3];
        }
    }
    __syncthreads();
    {
        int row = tid >> 2;
        int f0  = tid & 3;
        float4* op = (float4*)(out + (((size_t)(b * CC + row) * HH + h) * WW + w0));
        const float4* sp = (const float4*)(sOut + row * TPX);
        #pragma unroll
        for (int j = 0; j < 8; j++) op[f0 + j * 4] = sp[f0 + j * 4];
    }
}

// ---------------- launch ------------------------------------------------------
extern "C" void kernel_launch(void* const* d_in, const int* in_sizes, int n_in,
                              void* d_out, int out_size) {
    const float* x     = (const float*)d_in[0];
    const float* Woff  = (const float*)d_in[1];
    const float* boff  = (const float*)d_in[2];
    const float* Wd    = (const float*)d_in[3];
    const float* Wfuse = (const float*)d_in[4];
    float* out = (float*)d_out;

    int smem_main = SMF_TOT * 4;          // 77824
    int smem_off  = 2 * 130 * OSTR * 4;
    static int smem_set = 0;
    if (!smem_set) {
        cudaFuncSetAttribute(main_kernel,
                             cudaFuncAttributeMaxDynamicSharedMemorySize, smem_main);
        cudaFuncSetAttribute(offconv_kernel,
                             cudaFuncAttributeMaxDynamicSharedMemorySize, smem_off);
        smem_set = 1;
    }

    transpose_kernel<<<dim3(WW / 32, CC / 32, BB * HH), dim3(32, 8)>>>(x);
    weff_kernel<<<(ND * KK * CC * CC + 255) / 256, 256>>>(Wd, Wfuse);
    woff_kernel<<<(KK * CC * CC + 255) / 256, 256>>>(Woff);
    offconv_kernel<<<dim3(WW / TPX, BB * HH), 256, smem_off>>>(boff);
    main_kernel<<<dim3(WW / TPX, BB * HH), 256, smem_main>>>(out);
}

// round 10
// speedup vs baseline: 1.7409x; 1.3844x over previous
#include <cuda_runtime.h>
#include <cuda_fp16.h>
#include <cstdint>

#define BB   2
#define CC   64
#define HH   256
#define WW   256
#define KK   9
#define ND   3
#define NOFF 54
#define TPX  128         // pixels per main-kernel block
#define SH   72          // sS row stride in halves (64 + 8 pad = 144B)

typedef unsigned long long ull;
typedef unsigned int u32;

// m16n8k16 fp16 mma, fp32 accumulate (sm_80 baseline PTX -> HMMA on sm_103)
__device__ __forceinline__ void mma_f16(float* c,
                                        u32 a0, u32 a1, u32 a2, u32 a3,
                                        u32 b0, u32 b1) {
    asm("mma.sync.aligned.m16n8k16.row.col.f32.f16.f16.f32 "
        "{%0,%1,%2,%3}, {%4,%5,%6,%7}, {%8,%9}, {%0,%1,%2,%3};"
        : "+f"(c[0]), "+f"(c[1]), "+f"(c[2]), "+f"(c[3])
        : "r"(a0), "r"(a1), "r"(a2), "r"(a3), "r"(b0), "r"(b1));
}

// ---------------- scratch ----------------------------------------------------
// g_xT: fp16 NHWC, channel c stored at position P(c) (fragment-native order)
__device__ __half g_xT[(size_t)BB * HH * WW * CC];
__device__ float  g_offT[(size_t)BB * HH * NOFF * WW];     // offsets (bh, ch, w)
__device__ __half g_weffH[(size_t)ND * KK * CC * CC];      // frag-ordered fp16
__device__ __half g_woffH[(size_t)KK * CC * CC];           // offset-conv weights

// position of channel c within a 64-half row (A-fragment-native)
__device__ __forceinline__ int P_of(int c) {
    return (c >> 4) * 16 + ((c & 7) >> 1) * 4 + ((c >> 3) & 1) * 2 + (c & 1);
}
// half index within frag-ordered B array for (oo = n, c = k)
__device__ __forceinline__ int frag_index_h(int oo, int c) {
    int s = c >> 4, r = c & 15;
    int le = (r & 7) >> 1, hidx = ((r >> 3) << 1) | (r & 1);
    int wn = oo >> 5, nt = (oo >> 3) & 3, g = oo & 7;
    return ((((wn * 4 + s) * 4 + nt) * 32) + g * 4 + le) * 4 + hidx;
}

// ---------------- 1) transpose x -> fragment-ordered fp16 NHWC ----------------
__global__ void transpose_kernel(const float* __restrict__ x) {
    __shared__ float tile[32][33];
    int bh = blockIdx.z;
    int b  = bh / HH, h = bh % HH;
    int w0 = blockIdx.x * 32;
    int c0 = blockIdx.y * 32;
    int tx = threadIdx.x, ty = threadIdx.y;

    #pragma unroll
    for (int j = 0; j < 4; j++) {
        int c = c0 + ty + j * 8;
        tile[ty + j * 8][tx] = x[(((size_t)b * CC + c) * HH + h) * WW + (w0 + tx)];
    }
    __syncthreads();
    #pragma unroll
    for (int j = 0; j < 4; j++) {
        int w = w0 + ty + j * 8;
        int c = c0 + tx;
        g_xT[(((size_t)b * HH + h) * WW + w) * CC + P_of(c)] =
            __float2half(tile[tx][ty + j * 8]);
    }
}

// ---------------- 2a) Weff -> fragment-ordered fp16 ---------------------------
__global__ void weff_kernel(const float* __restrict__ Wd,
                            const float* __restrict__ Wfuse) {
    int idx = blockIdx.x * 256 + threadIdx.x;
    if (idx >= ND * KK * CC * CC) return;
    int oo = idx % CC;
    int c  = (idx / CC) % CC;
    int k  = (idx / (CC * CC)) % KK;
    int i  = idx / (CC * CC * KK);
    float acc = 0.f;
    #pragma unroll 8
    for (int o = 0; o < CC; o++) {
        acc = fmaf(Wfuse[oo * (ND * CC) + i * CC + o],
                   Wd[(((size_t)(i * CC + o) * CC + c) * KK) + k], acc);
    }
    int tap = i * KK + k;
    g_weffH[(size_t)tap * CC * CC + frag_index_h(oo, c)] = __float2half(acc);
}

// ---------------- 2b) Woff -> fragment-ordered fp16 (oc padded to 64) ---------
__global__ void woff_kernel(const float* __restrict__ Woff) {
    int idx = blockIdx.x * 256 + threadIdx.x;
    if (idx >= KK * CC * CC) return;
    int c  = idx % CC;
    int oc = (idx / CC) % CC;
    int k  = idx / (CC * CC);
    float v = (oc < NOFF) ? Woff[(size_t)oc * CC * KK + c * KK + k] : 0.f;
    g_woffH[(size_t)k * CC * CC + frag_index_h(oc, c)] = __float2half(v);
}

// ---------------- 3) offset conv via fp16 mma (9 shifted GEMMs) ---------------
// smem: sX[2][130*SH] halves (37440B); epilogue sOut 64x128 f32 (32768B)
__global__ __launch_bounds__(256, 2)
void offconv_kernel(const float* __restrict__ boff) {
    extern __shared__ u32 smo[];
    __half* sX = (__half*)smo;

    int bh = blockIdx.y;
    int b  = bh / HH, h = bh % HH;
    int w0 = blockIdx.x * TPX;
    int tid = threadIdx.x;
    int lane = tid & 31, wid = tid >> 5;
    int warp_m = wid >> 1;
    int warp_n = wid & 1;
    int lg = lane >> 2;
    int le = lane & 3;

    const __half* xTrow = g_xT + (size_t)b * HH * WW * CC;

    float acc[2][4][4];
    #pragma unroll
    for (int mt = 0; mt < 2; mt++)
        #pragma unroll
        for (int nt = 0; nt < 4; nt++)
            #pragma unroll
            for (int e = 0; e < 4; e++) acc[mt][nt][e] = 0.f;

    for (int ky = 0; ky < 3; ky++) {
        int row = h + ky - 1;
        if (row < 0 || row >= HH) continue;

        __half* sXp = sX + (ky & 1) * (130 * SH);
        {
            // pure copy: g_xT already fp16 in fragment-native channel order
            const uint4* src = (const uint4*)(xTrow + (size_t)row * WW * CC);
            for (int t = tid; t < 130 * 8; t += 256) {
                int px = t >> 3, ch = t & 7;
                int w = w0 - 1 + px;
                uint4 val = make_uint4(0u, 0u, 0u, 0u);
                if (w >= 0 && w < WW) val = __ldg(src + (size_t)w * 8 + ch);
                *(uint4*)&sXp[px * SH + ch * 8] = val;
            }
        }
        __syncthreads();

        #pragma unroll
        for (int kx = 0; kx < 3; kx++) {
            int k = ky * 3 + kx;
            const uint2* wF2 = (const uint2*)g_woffH + (size_t)k * 1024 + warp_n * 512;
            int abase = warp_m * 32 + kx;
            #pragma unroll
            for (int s2 = 0; s2 < 4; s2++) {
                int cofs = s2 * 16 + le * 4;
                uint2 a00 = *(const uint2*)&sXp[(abase + lg)      * SH + cofs];
                uint2 a01 = *(const uint2*)&sXp[(abase + lg + 8)  * SH + cofs];
                uint2 a10 = *(const uint2*)&sXp[(abase + lg + 16) * SH + cofs];
                uint2 a11 = *(const uint2*)&sXp[(abase + lg + 24) * SH + cofs];
                #pragma unroll
                for (int nt = 0; nt < 4; nt++) {
                    uint2 bv = __ldg(wF2 + (s2 * 4 + nt) * 32 + lane);
                    mma_f16(acc[0][nt], a00.x, a01.x, a00.y, a01.y, bv.x, bv.y);
                    mma_f16(acc[1][nt], a10.x, a11.x, a10.y, a11.y, bv.x, bv.y);
                }
            }
        }
        __syncthreads();
    }

    // epilogue: frags(+bias) -> smem [oc][px] -> coalesced g_offT stores
    float* sOut = (float*)smo;
    __syncthreads();
    #pragma unroll
    for (int mt = 0; mt < 2; mt++) {
        int px0 = warp_m * 32 + mt * 16 + lg;
        #pragma unroll
        for (int nt = 0; nt < 4; nt++) {
            int oc = warp_n * 32 + nt * 8 + 2 * le;
            float b0 = (oc < NOFF)     ? __ldg(&boff[oc])     : 0.f;
            float b1 = (oc + 1 < NOFF) ? __ldg(&boff[oc + 1]) : 0.f;
            sOut[oc * TPX + px0]           = acc[mt][nt][0] + b0;
            sOut[(oc + 1) * TPX + px0]     = acc[mt][nt][1] + b1;
            sOut[oc * TPX + px0 + 8]       = acc[mt][nt][2] + b0;
            sOut[(oc + 1) * TPX + px0 + 8] = acc[mt][nt][3] + b1;
        }
    }
    __syncthreads();
    {
        int oc = tid >> 2;
        int f0 = tid & 3;
        if (oc < NOFF) {
            float4* op = (float4*)(g_offT + ((size_t)bh * NOFF + oc) * WW + w0);
            const float4* sp = (const float4*)(sOut + oc * TPX);
            #pragma unroll
            for (int j = 0; j < 8; j++) op[f0 + j * 4] = sp[f0 + j * 4];
        }
    }
}

// ---------------- 4) main: fp16 gather + fp16 mma, double-buffered sS ---------
// smem: sS 2*128*SH halves (36864B) + sG 2*128*8 floats (8192B) = 45056B
#define SMF_G   ((2 * TPX * SH * 2) / 4)      // float offset of sG
#define SM_TOTAL (2 * TPX * SH * 2 + 2 * TPX * 8 * 4)

__global__ __launch_bounds__(256, 2)
void main_kernel(float* __restrict__ out) {
    extern __shared__ float sm[];
    float* sG = sm + SMF_G;

    int bh = blockIdx.y;
    int b  = bh / HH, h = bh % HH;
    int w0 = blockIdx.x * TPX;
    int tid = threadIdx.x;
    int lane = tid & 31, wid = tid >> 5;

    int grp = tid >> 4;           // gather group 0..15 (8 px each)
    int f   = tid & 15;           // 8B fp16 chunk lane (positions 4f..4f+3)
    int warp_m = wid >> 1;
    int warp_n = wid & 1;
    int lg = lane >> 2;
    int le = lane & 3;

    const char*  xTb  = (const char*)(g_xT + (size_t)b * HH * WW * CC);
    const float* offb = g_offT + (size_t)bh * NOFF * WW + w0;

    float acc[2][4][4];
    #pragma unroll
    for (int mt = 0; mt < 2; mt++)
        #pragma unroll
        for (int nt = 0; nt < 4; nt++)
            #pragma unroll
            for (int e = 0; e < 4; e++) acc[mt][nt][e] = 0.f;

    auto setup = [&](int tap, int buf) {
        if (tid < TPX) {
            int px = tid;
            int i = tap / KK, k = tap - i * KK;
            int d = 1 << i;
            float dy = __ldg(offb + (size_t)(i * 18 + 2 * k) * WW + px);
            float dx = __ldg(offb + (size_t)(i * 18 + 2 * k + 1) * WW + px);
            float ys  = (float)h + (float)((k / 3 - 1) * d) + dy;
            float xsf = (float)(w0 + px) + (float)((k % 3 - 1) * d) + dx;
            float y0f = floorf(ys), x0f = floorf(xsf);
            float wy1 = ys - y0f, wx1 = xsf - x0f, wy0 = 1.f - wy1, wx0 = 1.f - wx1;
            float y1f = y0f + 1.f, x1f = x0f + 1.f;
            float vy0 = (y0f >= 0.f && y0f <= 255.f) ? 1.f : 0.f;
            float vy1 = (y1f >= 0.f && y1f <= 255.f) ? 1.f : 0.f;
            float vx0 = (x0f >= 0.f && x0f <= 255.f) ? 1.f : 0.f;
            float vx1 = (x1f >= 0.f && x1f <= 255.f) ? 1.f : 0.f;
            u32 iy0 = (u32)(int)fminf(fmaxf(y0f, 0.f), 255.f);
            u32 iy1 = (u32)(int)fminf(fmaxf(y1f, 0.f), 255.f);
            u32 ix0 = (u32)(int)fminf(fmaxf(x0f, 0.f), 255.f);
            u32 ix1 = (u32)(int)fminf(fmaxf(x1f, 0.f), 255.f);
            uint4 o;
            o.x = ((iy0 * WW + ix0) * CC) * 2u;   // BYTE offsets (fp16)
            o.y = ((iy0 * WW + ix1) * CC) * 2u;
            o.z = ((iy1 * WW + ix0) * CC) * 2u;
            o.w = ((iy1 * WW + ix1) * CC) * 2u;
            float4 cw = make_float4(wy0 * wx0 * vy0 * vx0, wy0 * wx1 * vy0 * vx1,
                                    wy1 * wx0 * vy1 * vx0, wy1 * wx1 * vy1 * vx1);
            *(uint4*) &sG[(buf * TPX + px) * 8]     = o;
            *(float4*)&sG[(buf * TPX + px) * 8 + 4] = cw;
        }
    };

    setup(0, 0);
    __syncthreads();

    for (int tap = 0; tap < ND * KK; tap++) {
        int p = tap & 1;
        __half* sS16 = (__half*)sm + p * (TPX * SH);

        // gather tap -> sS[p]: 8-deep pipelined fp16 loads, uint2 STS
        {
            const float* gp = &sG[(p * TPX + grp * 8) * 8];
            uint4  o  = *(const uint4*) (gp);
            float4 cw = *(const float4*)(gp + 4);
            uint2 c0 = __ldg((const uint2*)(xTb + o.x) + f);
            uint2 c1 = __ldg((const uint2*)(xTb + o.y) + f);
            uint2 c2 = __ldg((const uint2*)(xTb + o.z) + f);
            uint2 c3 = __ldg((const uint2*)(xTb + o.w) + f);

            #pragma unroll
            for (int j = 0; j < 8; j++) {
                uint4 no; float4 ncw;
                uint2 n0, n1, n2, n3;
                if (j < 7) {
                    const float* gq = &sG[(p * TPX + grp * 8 + j + 1) * 8];
                    no  = *(const uint4*) (gq);
                    ncw = *(const float4*)(gq + 4);
                    n0 = __ldg((const uint2*)(xTb + no.x) + f);
                    n1 = __ldg((const uint2*)(xTb + no.y) + f);
                    n2 = __ldg((const uint2*)(xTb + no.z) + f);
                    n3 = __ldg((const uint2*)(xTb + no.w) + f);
                }
                float2 a0 = __half22float2(*(const __half2*)&c0.x);
                float2 a1 = __half22float2(*(const __half2*)&c0.y);
                float2 b0 = __half22float2(*(const __half2*)&c1.x);
                float2 b1 = __half22float2(*(const __half2*)&c1.y);
                float2 d0 = __half22float2(*(const __half2*)&c2.x);
                float2 d1 = __half22float2(*(const __half2*)&c2.y);
                float2 e0 = __half22float2(*(const __half2*)&c3.x);
                float2 e1 = __half22float2(*(const __half2*)&c3.y);
                float r0 = cw.x*a0.x + cw.y*b0.x + cw.z*d0.x + cw.w*e0.x;
                float r1 = cw.x*a0.y + cw.y*b0.y + cw.z*d0.y + cw.w*e0.y;
                float r2 = cw.x*a1.x + cw.y*b1.x + cw.z*d1.x + cw.w*e1.x;
                float r3 = cw.x*a1.y + cw.y*b1.y + cw.z*d1.y + cw.w*e1.y;
                __half2 h01 = __floats2half2_rn(r0, r1);
                __half2 h23 = __floats2half2_rn(r2, r3);
                uint2 wv;
                wv.x = *(u32*)&h01;
                wv.y = *(u32*)&h23;
                *(uint2*)&sS16[(grp * 8 + j) * SH + 4 * f] = wv;
                if (j < 7) { o = no; cw = ncw; c0 = n0; c1 = n1; c2 = n2; c3 = n3; }
            }
        }

        // stage next tap's bilinear setup into sG[1-p]
        if (tap + 1 < ND * KK) setup(tap + 1, 1 - p);

        __syncthreads();   // only sync this tap

        // einsum: A uint2 LDS from sS[p], B uint2 LDG (L1-hit), fp16 HMMA
        {
            const uint2* wF2 = (const uint2*)g_weffH + (size_t)tap * 1024 + warp_n * 512;
            int arow = warp_m * 32 + lg;
            #pragma unroll
            for (int s2 = 0; s2 < 4; s2++) {
                int cofs = s2 * 16 + le * 4;
                uint2 a00 = *(const uint2*)&sS16[(arow)      * SH + cofs];
                uint2 a01 = *(const uint2*)&sS16[(arow + 8)  * SH + cofs];
                uint2 a10 = *(const uint2*)&sS16[(arow + 16) * SH + cofs];
                uint2 a11 = *(const uint2*)&sS16[(arow + 24) * SH + cofs];
                #pragma unroll
                for (int nt = 0; nt < 4; nt++) {
                    uint2 bv = __ldg(wF2 + (s2 * 4 + nt) * 32 + lane);
                    mma_f16(acc[0][nt], a00.x, a01.x, a00.y, a01.y, bv.x, bv.y);
                    mma_f16(acc[1][nt], a10.x, a11.x, a10.y, a11.y, bv.x, bv.y);
                }
            }
        }
        // no trailing sync: next gather targets the other sS buffer
    }

    // epilogue: frags -> smem [oo][px] -> coalesced stores
    __syncthreads();
    float* sOut = sm;
    #pragma unroll
    for (int mt = 0; mt < 2; mt++) {
        int px0 = warp_m * 32 + mt * 16 + lg;
        #pragma unroll
        for (int nt = 0; nt < 4; nt++) {
            int oo = warp_n * 32 + nt * 8 + 2 * le;
            sOut[oo * TPX + px0]           = acc[mt][nt][0];
            sOut[(oo + 1) * TPX + px0]     = acc[mt][nt][1];
            sOut[oo * TPX + px0 + 8]       = acc[mt][nt][2];
            sOut[(oo + 1) * TPX + px0 + 8] = acc[mt][nt][3];
        }
    }
    __syncthreads();
    {
        int row = tid >> 2;
        int f0  = tid & 3;
        float4* op = (float4*)(out + (((size_t)(b * CC + row) * HH + h) * WW + w0));
        const float4* sp = (const float4*)(sOut + row * TPX);
        #pragma unroll
        for (int j = 0; j < 8; j++) op[f0 + j * 4] = sp[f0 + j * 4];
    }
}

// ---------------- launch ------------------------------------------------------
extern "C" void kernel_launch(void* const* d_in, const int* in_sizes, int n_in,
                              void* d_out, int out_size) {
    const float* x     = (const float*)d_in[0];
    const float* Woff  = (const float*)d_in[1];
    const float* boff  = (const float*)d_in[2];
    const float* Wd    = (const float*)d_in[3];
    const float* Wfuse = (const float*)d_in[4];
    float* out = (float*)d_out;

    int smem_main = SM_TOTAL;                 // 45056
    int smem_off  = 2 * 130 * SH * 2;         // 37440 (>= 32768 epilogue)
    static int smem_set = 0;
    if (!smem_set) {
        cudaFuncSetAttribute(main_kernel,
                             cudaFuncAttributeMaxDynamicSharedMemorySize, smem_main);
        cudaFuncSetAttribute(offconv_kernel,
                             cudaFuncAttributeMaxDynamicSharedMemorySize, smem_off);
        smem_set = 1;
    }

    transpose_kernel<<<dim3(WW / 32, CC / 32, BB * HH), dim3(32, 8)>>>(x);
    weff_kernel<<<(ND * KK * CC * CC + 255) / 256, 256>>>(Wd, Wfuse);
    woff_kernel<<<(KK * CC * CC + 255) / 256, 256>>>(Woff);
    offconv_kernel<<<dim3(WW / TPX, BB * HH), 256, smem_off>>>(boff);
    main_kernel<<<dim3(WW / TPX, BB * HH), 256, smem_main>>>(out);
}

// round 11
// speedup vs baseline: 1.7920x; 1.0294x over previous
#include <cuda_runtime.h>
#include <cuda_fp16.h>
#include <cstdint>

#define BB   2
#define CC   64
#define HH   256
#define WW   256
#define KK   9
#define ND   3
#define NOFF 54
#define TPX  128         // pixels per main-kernel block
#define SH   72          // sS row stride in halves (64 + 8 pad = 144B)

typedef unsigned long long ull;
typedef unsigned int u32;

// m16n8k16 fp16 mma, fp32 accumulate (sm_80 baseline PTX -> HMMA on sm_103)
__device__ __forceinline__ void mma_f16(float* c,
                                        u32 a0, u32 a1, u32 a2, u32 a3,
                                        u32 b0, u32 b1) {
    asm("mma.sync.aligned.m16n8k16.row.col.f32.f16.f16.f32 "
        "{%0,%1,%2,%3}, {%4,%5,%6,%7}, {%8,%9}, {%0,%1,%2,%3};"
        : "+f"(c[0]), "+f"(c[1]), "+f"(c[2]), "+f"(c[3])
        : "r"(a0), "r"(a1), "r"(a2), "r"(a3), "r"(b0), "r"(b1));
}

// ---------------- scratch ----------------------------------------------------
// g_xT: fp16 NHWC, channel c stored at position P(c) (fragment-native order)
__device__ __half g_xT[(size_t)BB * HH * WW * CC];
__device__ float  g_offT[(size_t)BB * HH * NOFF * WW];     // offsets (bh, ch, w)
__device__ __half g_weffH[(size_t)ND * KK * CC * CC];      // frag-ordered fp16
__device__ __half g_woffH[(size_t)KK * CC * CC];           // offset-conv weights

// position of channel c within a 64-half row (A-fragment-native)
__device__ __forceinline__ int P_of(int c) {
    return (c >> 4) * 16 + ((c & 7) >> 1) * 4 + ((c >> 3) & 1) * 2 + (c & 1);
}
// half index within frag-ordered B array for (oo = n, c = k)
__device__ __forceinline__ int frag_index_h(int oo, int c) {
    int s = c >> 4, r = c & 15;
    int le = (r & 7) >> 1, hidx = ((r >> 3) << 1) | (r & 1);
    int wn = oo >> 5, nt = (oo >> 3) & 3, g = oo & 7;
    return ((((wn * 4 + s) * 4 + nt) * 32) + g * 4 + le) * 4 + hidx;
}

// ---------------- 1) transpose x -> fragment-ordered fp16 NHWC ----------------
__global__ void transpose_kernel(const float* __restrict__ x) {
    __shared__ float tile[32][33];
    int bh = blockIdx.z;
    int b  = bh / HH, h = bh % HH;
    int w0 = blockIdx.x * 32;
    int c0 = blockIdx.y * 32;
    int tx = threadIdx.x, ty = threadIdx.y;

    #pragma unroll
    for (int j = 0; j < 4; j++) {
        int c = c0 + ty + j * 8;
        tile[ty + j * 8][tx] = x[(((size_t)b * CC + c) * HH + h) * WW + (w0 + tx)];
    }
    __syncthreads();
    #pragma unroll
    for (int j = 0; j < 4; j++) {
        int w = w0 + ty + j * 8;
        int c = c0 + tx;
        g_xT[(((size_t)b * HH + h) * WW + w) * CC + P_of(c)] =
            __float2half(tile[tx][ty + j * 8]);
    }
}

// ---------------- 2a) Weff -> fragment-ordered fp16 ---------------------------
__global__ void weff_kernel(const float* __restrict__ Wd,
                            const float* __restrict__ Wfuse) {
    int idx = blockIdx.x * 256 + threadIdx.x;
    if (idx >= ND * KK * CC * CC) return;
    int oo = idx % CC;
    int c  = (idx / CC) % CC;
    int k  = (idx / (CC * CC)) % KK;
    int i  = idx / (CC * CC * KK);
    float acc = 0.f;
    #pragma unroll 8
    for (int o = 0; o < CC; o++) {
        acc = fmaf(Wfuse[oo * (ND * CC) + i * CC + o],
                   Wd[(((size_t)(i * CC + o) * CC + c) * KK) + k], acc);
    }
    int tap = i * KK + k;
    g_weffH[(size_t)tap * CC * CC + frag_index_h(oo, c)] = __float2half(acc);
}

// ---------------- 2b) Woff -> fragment-ordered fp16 (oc padded to 64) ---------
__global__ void woff_kernel(const float* __restrict__ Woff) {
    int idx = blockIdx.x * 256 + threadIdx.x;
    if (idx >= KK * CC * CC) return;
    int c  = idx % CC;
    int oc = (idx / CC) % CC;
    int k  = idx / (CC * CC);
    float v = (oc < NOFF) ? Woff[(size_t)oc * CC * KK + c * KK + k] : 0.f;
    g_woffH[(size_t)k * CC * CC + frag_index_h(oc, c)] = __float2half(v);
}

// ---------------- 3) offset conv via fp16 mma, 1 sync per ky -------------------
// smem: sX[2][130*SH] halves (37440B); epilogue sOut 64x128 f32 (32768B)
__global__ __launch_bounds__(256, 2)
void offconv_kernel(const float* __restrict__ boff) {
    extern __shared__ u32 smo[];
    __half* sX = (__half*)smo;

    int bh = blockIdx.y;
    int b  = bh / HH, h = bh % HH;
    int w0 = blockIdx.x * TPX;
    int tid = threadIdx.x;
    int lane = tid & 31, wid = tid >> 5;
    int warp_m = wid >> 1;
    int warp_n = wid & 1;
    int lg = lane >> 2;
    int le = lane & 3;

    const __half* xTrow = g_xT + (size_t)b * HH * WW * CC;

    float acc[2][4][4];
    #pragma unroll
    for (int mt = 0; mt < 2; mt++)
        #pragma unroll
        for (int nt = 0; nt < 4; nt++)
            #pragma unroll
            for (int e = 0; e < 4; e++) acc[mt][nt][e] = 0.f;

    // 1 sync per ky: stage(ky)->buf[ky&1], sync, mma(ky).
    // stage(ky) overlaps laggard warps' mma(ky-1) in the OTHER buffer;
    // mma(ky-2,same buf) finished before the sync of iter ky-1.
    for (int ky = 0; ky < 3; ky++) {
        int row = h + ky - 1;
        bool valid = (row >= 0 && row < HH);
        __half* sXp = sX + (ky & 1) * (130 * SH);

        if (valid) {
            // pure copy: g_xT already fp16 in fragment-native channel order
            const uint4* src = (const uint4*)(xTrow + (size_t)row * WW * CC);
            for (int t = tid; t < 130 * 8; t += 256) {
                int px = t >> 3, ch = t & 7;
                int w = w0 - 1 + px;
                uint4 val = make_uint4(0u, 0u, 0u, 0u);
                if (w >= 0 && w < WW) val = __ldg(src + (size_t)w * 8 + ch);
                *(uint4*)&sXp[px * SH + ch * 8] = val;
            }
        }
        __syncthreads();

        if (valid) {
            #pragma unroll
            for (int kx = 0; kx < 3; kx++) {
                int k = ky * 3 + kx;
                const uint2* wF2 = (const uint2*)g_woffH + (size_t)k * 1024 + warp_n * 512;
                int abase = warp_m * 32 + kx;
                #pragma unroll
                for (int s2 = 0; s2 < 4; s2++) {
                    int cofs = s2 * 16 + le * 4;
                    uint2 a00 = *(const uint2*)&sXp[(abase + lg)      * SH + cofs];
                    uint2 a01 = *(const uint2*)&sXp[(abase + lg + 8)  * SH + cofs];
                    uint2 a10 = *(const uint2*)&sXp[(abase + lg + 16) * SH + cofs];
                    uint2 a11 = *(const uint2*)&sXp[(abase + lg + 24) * SH + cofs];
                    #pragma unroll
                    for (int nt = 0; nt < 4; nt++) {
                        uint2 bv = __ldg(wF2 + (s2 * 4 + nt) * 32 + lane);
                        mma_f16(acc[0][nt], a00.x, a01.x, a00.y, a01.y, bv.x, bv.y);
                        mma_f16(acc[1][nt], a10.x, a11.x, a10.y, a11.y, bv.x, bv.y);
                    }
                }
            }
        }
    }

    // epilogue: frags(+bias) -> smem [oc][px] -> coalesced g_offT stores
    float* sOut = (float*)smo;
    __syncthreads();
    #pragma unroll
    for (int mt = 0; mt < 2; mt++) {
        int px0 = warp_m * 32 + mt * 16 + lg;
        #pragma unroll
        for (int nt = 0; nt < 4; nt++) {
            int oc = warp_n * 32 + nt * 8 + 2 * le;
            float b0 = (oc < NOFF)     ? __ldg(&boff[oc])     : 0.f;
            float b1 = (oc + 1 < NOFF) ? __ldg(&boff[oc + 1]) : 0.f;
            sOut[oc * TPX + px0]           = acc[mt][nt][0] + b0;
            sOut[(oc + 1) * TPX + px0]     = acc[mt][nt][1] + b1;
            sOut[oc * TPX + px0 + 8]       = acc[mt][nt][2] + b0;
            sOut[(oc + 1) * TPX + px0 + 8] = acc[mt][nt][3] + b1;
        }
    }
    __syncthreads();
    {
        int oc = tid >> 2;
        int f0 = tid & 3;
        if (oc < NOFF) {
            float4* op = (float4*)(g_offT + ((size_t)bh * NOFF + oc) * WW + w0);
            const float4* sp = (const float4*)(sOut + oc * TPX);
            #pragma unroll
            for (int j = 0; j < 8; j++) op[f0 + j * 4] = sp[f0 + j * 4];
        }
    }
}

// ---------------- 4) main: fp16 gather + fp16 mma, 3 CTAs/SM ------------------
// smem: sS 2*128*SH halves (36864B) + sG 2*128*8 floats (8192B) = 45056B
#define SMF_G   ((2 * TPX * SH * 2) / 4)      // float offset of sG
#define SM_TOTAL (2 * TPX * SH * 2 + 2 * TPX * 8 * 4)

__global__ __launch_bounds__(256, 3)
void main_kernel(float* __restrict__ out) {
    extern __shared__ float sm[];
    float* sG = sm + SMF_G;

    int bh = blockIdx.y;
    int b  = bh / HH, h = bh % HH;
    int w0 = blockIdx.x * TPX;
    int tid = threadIdx.x;
    int lane = tid & 31, wid = tid >> 5;

    int grp = tid >> 4;           // gather group 0..15 (8 px each)
    int f   = tid & 15;           // 8B fp16 chunk lane (positions 4f..4f+3)
    int warp_m = wid >> 1;
    int warp_n = wid & 1;
    int lg = lane >> 2;
    int le = lane & 3;

    const char*  xTb  = (const char*)(g_xT + (size_t)b * HH * WW * CC);
    const float* offb = g_offT + (size_t)bh * NOFF * WW + w0;

    float acc[2][4][4];
    #pragma unroll
    for (int mt = 0; mt < 2; mt++)
        #pragma unroll
        for (int nt = 0; nt < 4; nt++)
            #pragma unroll
            for (int e = 0; e < 4; e++) acc[mt][nt][e] = 0.f;

    auto setup = [&](int tap, int buf) {
        if (tid < TPX) {
            int px = tid;
            int i = tap / KK, k = tap - i * KK;
            int d = 1 << i;
            float dy = __ldg(offb + (size_t)(i * 18 + 2 * k) * WW + px);
            float dx = __ldg(offb + (size_t)(i * 18 + 2 * k + 1) * WW + px);
            float ys  = (float)h + (float)((k / 3 - 1) * d) + dy;
            float xsf = (float)(w0 + px) + (float)((k % 3 - 1) * d) + dx;
            float y0f = floorf(ys), x0f = floorf(xsf);
            float wy1 = ys - y0f, wx1 = xsf - x0f, wy0 = 1.f - wy1, wx0 = 1.f - wx1;
            float y1f = y0f + 1.f, x1f = x0f + 1.f;
            float vy0 = (y0f >= 0.f && y0f <= 255.f) ? 1.f : 0.f;
            float vy1 = (y1f >= 0.f && y1f <= 255.f) ? 1.f : 0.f;
            float vx0 = (x0f >= 0.f && x0f <= 255.f) ? 1.f : 0.f;
            float vx1 = (x1f >= 0.f && x1f <= 255.f) ? 1.f : 0.f;
            u32 iy0 = (u32)(int)fminf(fmaxf(y0f, 0.f), 255.f);
            u32 iy1 = (u32)(int)fminf(fmaxf(y1f, 0.f), 255.f);
            u32 ix0 = (u32)(int)fminf(fmaxf(x0f, 0.f), 255.f);
            u32 ix1 = (u32)(int)fminf(fmaxf(x1f, 0.f), 255.f);
            uint4 o;
            o.x = ((iy0 * WW + ix0) * CC) * 2u;   // BYTE offsets (fp16)
            o.y = ((iy0 * WW + ix1) * CC) * 2u;
            o.z = ((iy1 * WW + ix0) * CC) * 2u;
            o.w = ((iy1 * WW + ix1) * CC) * 2u;
            float4 cw = make_float4(wy0 * wx0 * vy0 * vx0, wy0 * wx1 * vy0 * vx1,
                                    wy1 * wx0 * vy1 * vx0, wy1 * wx1 * vy1 * vx1);
            *(uint4*) &sG[(buf * TPX + px) * 8]     = o;
            *(float4*)&sG[(buf * TPX + px) * 8 + 4] = cw;
        }
    };

    setup(0, 0);
    __syncthreads();

    for (int tap = 0; tap < ND * KK; tap++) {
        int p = tap & 1;
        __half* sS16 = (__half*)sm + p * (TPX * SH);

        // gather tap -> sS[p]: 8-deep pipelined fp16 loads, uint2 STS
        {
            const float* gp = &sG[(p * TPX + grp * 8) * 8];
            uint4  o  = *(const uint4*) (gp);
            float4 cw = *(const float4*)(gp + 4);
            uint2 c0 = __ldg((const uint2*)(xTb + o.x) + f);
            uint2 c1 = __ldg((const uint2*)(xTb + o.y) + f);
            uint2 c2 = __ldg((const uint2*)(xTb + o.z) + f);
            uint2 c3 = __ldg((const uint2*)(xTb + o.w) + f);

            #pragma unroll
            for (int j = 0; j < 8; j++) {
                uint4 no; float4 ncw;
                uint2 n0, n1, n2, n3;
                if (j < 7) {
                    const float* gq = &sG[(p * TPX + grp * 8 + j + 1) * 8];
                    no  = *(const uint4*) (gq);
                    ncw = *(const float4*)(gq + 4);
                    n0 = __ldg((const uint2*)(xTb + no.x) + f);
                    n1 = __ldg((const uint2*)(xTb + no.y) + f);
                    n2 = __ldg((const uint2*)(xTb + no.z) + f);
                    n3 = __ldg((const uint2*)(xTb + no.w) + f);
                }
                float2 a0 = __half22float2(*(const __half2*)&c0.x);
                float2 a1 = __half22float2(*(const __half2*)&c0.y);
                float2 b0 = __half22float2(*(const __half2*)&c1.x);
                float2 b1 = __half22float2(*(const __half2*)&c1.y);
                float2 d0 = __half22float2(*(const __half2*)&c2.x);
                float2 d1 = __half22float2(*(const __half2*)&c2.y);
                float2 e0 = __half22float2(*(const __half2*)&c3.x);
                float2 e1 = __half22float2(*(const __half2*)&c3.y);
                float r0 = cw.x*a0.x + cw.y*b0.x + cw.z*d0.x + cw.w*e0.x;
                float r1 = cw.x*a0.y + cw.y*b0.y + cw.z*d0.y + cw.w*e0.y;
                float r2 = cw.x*a1.x + cw.y*b1.x + cw.z*d1.x + cw.w*e1.x;
                float r3 = cw.x*a1.y + cw.y*b1.y + cw.z*d1.y + cw.w*e1.y;
                __half2 h01 = __floats2half2_rn(r0, r1);
                __half2 h23 = __floats2half2_rn(r2, r3);
                uint2 wv;
                wv.x = *(u32*)&h01;
                wv.y = *(u32*)&h23;
                *(uint2*)&sS16[(grp * 8 + j) * SH + 4 * f] = wv;
                if (j < 7) { o = no; cw = ncw; c0 = n0; c1 = n1; c2 = n2; c3 = n3; }
            }
        }

        // stage next tap's bilinear setup into sG[1-p]
        if (tap + 1 < ND * KK) setup(tap + 1, 1 - p);

        __syncthreads();   // only sync this tap

        // einsum: A uint2 LDS from sS[p], B uint2 LDG (L1-hit), fp16 HMMA
        {
            const uint2* wF2 = (const uint2*)g_weffH + (size_t)tap * 1024 + warp_n * 512;
            int arow = warp_m * 32 + lg;
            #pragma unroll
            for (int s2 = 0; s2 < 4; s2++) {
                int cofs = s2 * 16 + le * 4;
                uint2 a00 = *(const uint2*)&sS16[(arow)      * SH + cofs];
                uint2 a01 = *(const uint2*)&sS16[(arow + 8)  * SH + cofs];
                uint2 a10 = *(const uint2*)&sS16[(arow + 16) * SH + cofs];
                uint2 a11 = *(const uint2*)&sS16[(arow + 24) * SH + cofs];
                #pragma unroll
                for (int nt = 0; nt < 4; nt++) {
                    uint2 bv = __ldg(wF2 + (s2 * 4 + nt) * 32 + lane);
                    mma_f16(acc[0][nt], a00.x, a01.x, a00.y, a01.y, bv.x, bv.y);
                    mma_f16(acc[1][nt], a10.x, a11.x, a10.y, a11.y, bv.x, bv.y);
                }
            }
        }
        // no trailing sync: next gather targets the other sS buffer
    }

    // epilogue: frags -> smem [oo][px] -> coalesced stores
    __syncthreads();
    float* sOut = sm;
    #pragma unroll
    for (int mt = 0; mt < 2; mt++) {
        int px0 = warp_m * 32 + mt * 16 + lg;
        #pragma unroll
        for (int nt = 0; nt < 4; nt++) {
            int oo = warp_n * 32 + nt * 8 + 2 * le;
            sOut[oo * TPX + px0]           = acc[mt][nt][0];
            sOut[(oo + 1) * TPX + px0]     = acc[mt][nt][1];
            sOut[oo * TPX + px0 + 8]       = acc[mt][nt][2];
            sOut[(oo + 1) * TPX + px0 + 8] = acc[mt][nt][3];
        }
    }
    __syncthreads();
    {
        int row = tid >> 2;
        int f0  = tid & 3;
        float4* op = (float4*)(out + (((size_t)(b * CC + row) * HH + h) * WW + w0));
        const float4* sp = (const float4*)(sOut + row * TPX);
        #pragma unroll
        for (int j = 0; j < 8; j++) op[f0 + j * 4] = sp[f0 + j * 4];
    }
}

// ---------------- launch ------------------------------------------------------
extern "C" void kernel_launch(void* const* d_in, const int* in_sizes, int n_in,
                              void* d_out, int out_size) {
    const float* x     = (const float*)d_in[0];
    const float* Woff  = (const float*)d_in[1];
    const float* boff  = (const float*)d_in[2];
    const float* Wd    = (const float*)d_in[3];
    const float* Wfuse = (const float*)d_in[4];
    float* out = (float*)d_out;

    int smem_main = SM_TOTAL;                 // 45056
    int smem_off  = 2 * 130 * SH * 2;         // 37440 (>= 32768 epilogue)
    static int smem_set = 0;
    if (!smem_set) {
        cudaFuncSetAttribute(main_kernel,
                             cudaFuncAttributeMaxDynamicSharedMemorySize, smem_main);
        cudaFuncSetAttribute(offconv_kernel,
                             cudaFuncAttributeMaxDynamicSharedMemorySize, smem_off);
        smem_set = 1;
    }

    transpose_kernel<<<dim3(WW / 32, CC / 32, BB * HH), dim3(32, 8)>>>(x);
    weff_kernel<<<(ND * KK * CC * CC + 255) / 256, 256>>>(Wd, Wfuse);
    woff_kernel<<<(KK * CC * CC + 255) / 256, 256>>>(Woff);
    offconv_kernel<<<dim3(WW / TPX, BB * HH), 256, smem_off>>>(boff);
    main_kernel<<<dim3(WW / TPX, BB * HH), 256, smem_main>>>(out);
}

// round 12
// speedup vs baseline: 1.9040x; 1.0625x over previous
#include <cuda_runtime.h>
#include <cuda_fp16.h>
#include <cstdint>

#define BB   2
#define CC   64
#define HH   256
#define WW   256
#define KK   9
#define ND   3
#define NOFF 54
#define TPX  128         // pixels per main-kernel block
#define SH   72          // sS row stride in halves (64 + 8 pad = 144B)

typedef unsigned long long ull;
typedef unsigned int u32;

// m16n8k16 fp16 mma, fp32 accumulate (sm_80 baseline PTX -> HMMA on sm_103)
__device__ __forceinline__ void mma_f16(float* c,
                                        u32 a0, u32 a1, u32 a2, u32 a3,
                                        u32 b0, u32 b1) {
    asm("mma.sync.aligned.m16n8k16.row.col.f32.f16.f16.f32 "
        "{%0,%1,%2,%3}, {%4,%5,%6,%7}, {%8,%9}, {%0,%1,%2,%3};"
        : "+f"(c[0]), "+f"(c[1]), "+f"(c[2]), "+f"(c[3])
        : "r"(a0), "r"(a1), "r"(a2), "r"(a3), "r"(b0), "r"(b1));
}

// ---------------- scratch ----------------------------------------------------
__device__ __half g_xT[(size_t)BB * HH * WW * CC];         // fp16, P(c)-ordered NHWC
__device__ float  g_offT[(size_t)BB * HH * NOFF * WW];     // offsets (bh, ch, w)
__device__ __half g_weffH[(size_t)ND * KK * CC * CC];      // frag-ordered fp16
__device__ __half g_woffH[(size_t)KK * CC * CC];           // offset-conv weights

__device__ __forceinline__ int P_of(int c) {
    return (c >> 4) * 16 + ((c & 7) >> 1) * 4 + ((c >> 3) & 1) * 2 + (c & 1);
}
__device__ __forceinline__ int frag_index_h(int oo, int c) {
    int s = c >> 4, r = c & 15;
    int le = (r & 7) >> 1, hidx = ((r >> 3) << 1) | (r & 1);
    int wn = oo >> 5, nt = (oo >> 3) & 3, g = oo & 7;
    return ((((wn * 4 + s) * 4 + nt) * 32) + g * 4 + le) * 4 + hidx;
}

// ---------------- 1) transpose x -> fragment-ordered fp16 NHWC ----------------
__global__ void transpose_kernel(const float* __restrict__ x) {
    __shared__ float tile[32][33];
    int bh = blockIdx.z;
    int b  = bh / HH, h = bh % HH;
    int w0 = blockIdx.x * 32;
    int c0 = blockIdx.y * 32;
    int tx = threadIdx.x, ty = threadIdx.y;

    #pragma unroll
    for (int j = 0; j < 4; j++) {
        int c = c0 + ty + j * 8;
        tile[ty + j * 8][tx] = x[(((size_t)b * CC + c) * HH + h) * WW + (w0 + tx)];
    }
    __syncthreads();
    #pragma unroll
    for (int j = 0; j < 4; j++) {
        int w = w0 + ty + j * 8;
        int c = c0 + tx;
        g_xT[(((size_t)b * HH + h) * WW + w) * CC + P_of(c)] =
            __float2half(tile[tx][ty + j * 8]);
    }
}

// ---------------- 2a) Weff -> fragment-ordered fp16 ---------------------------
__global__ void weff_kernel(const float* __restrict__ Wd,
                            const float* __restrict__ Wfuse) {
    int idx = blockIdx.x * 256 + threadIdx.x;
    if (idx >= ND * KK * CC * CC) return;
    int oo = idx % CC;
    int c  = (idx / CC) % CC;
    int k  = (idx / (CC * CC)) % KK;
    int i  = idx / (CC * CC * KK);
    float acc = 0.f;
    #pragma unroll 8
    for (int o = 0; o < CC; o++) {
        acc = fmaf(Wfuse[oo * (ND * CC) + i * CC + o],
                   Wd[(((size_t)(i * CC + o) * CC + c) * KK) + k], acc);
    }
    int tap = i * KK + k;
    g_weffH[(size_t)tap * CC * CC + frag_index_h(oo, c)] = __float2half(acc);
}

// ---------------- 2b) Woff -> fragment-ordered fp16 ---------------------------
__global__ void woff_kernel(const float* __restrict__ Woff) {
    int idx = blockIdx.x * 256 + threadIdx.x;
    if (idx >= KK * CC * CC) return;
    int c  = idx % CC;
    int oc = (idx / CC) % CC;
    int k  = idx / (CC * CC);
    float v = (oc < NOFF) ? Woff[(size_t)oc * CC * KK + c * KK + k] : 0.f;
    g_woffH[(size_t)k * CC * CC + frag_index_h(oc, c)] = __float2half(v);
}

// ---------------- 3) offset conv via fp16 mma, 1 sync per ky -------------------
__global__ __launch_bounds__(256, 2)
void offconv_kernel(const float* __restrict__ boff) {
    extern __shared__ u32 smo[];
    __half* sX = (__half*)smo;

    int bh = blockIdx.y;
    int b  = bh / HH, h = bh % HH;
    int w0 = blockIdx.x * TPX;
    int tid = threadIdx.x;
    int lane = tid & 31, wid = tid >> 5;
    int warp_m = wid >> 1;
    int warp_n = wid & 1;
    int lg = lane >> 2;
    int le = lane & 3;

    const __half* xTrow = g_xT + (size_t)b * HH * WW * CC;

    float acc[2][4][4];
    #pragma unroll
    for (int mt = 0; mt < 2; mt++)
        #pragma unroll
        for (int nt = 0; nt < 4; nt++)
            #pragma unroll
            for (int e = 0; e < 4; e++) acc[mt][nt][e] = 0.f;

    for (int ky = 0; ky < 3; ky++) {
        int row = h + ky - 1;
        bool valid = (row >= 0 && row < HH);
        __half* sXp = sX + (ky & 1) * (130 * SH);

        if (valid) {
            const uint4* src = (const uint4*)(xTrow + (size_t)row * WW * CC);
            for (int t = tid; t < 130 * 8; t += 256) {
                int px = t >> 3, ch = t & 7;
                int w = w0 - 1 + px;
                uint4 val = make_uint4(0u, 0u, 0u, 0u);
                if (w >= 0 && w < WW) val = __ldg(src + (size_t)w * 8 + ch);
                *(uint4*)&sXp[px * SH + ch * 8] = val;
            }
        }
        __syncthreads();

        if (valid) {
            #pragma unroll
            for (int kx = 0; kx < 3; kx++) {
                int k = ky * 3 + kx;
                const uint2* wF2 = (const uint2*)g_woffH + (size_t)k * 1024 + warp_n * 512;
                int abase = warp_m * 32 + kx;
                #pragma unroll
                for (int s2 = 0; s2 < 4; s2++) {
                    int cofs = s2 * 16 + le * 4;
                    uint2 a00 = *(const uint2*)&sXp[(abase + lg)      * SH + cofs];
                    uint2 a01 = *(const uint2*)&sXp[(abase + lg + 8)  * SH + cofs];
                    uint2 a10 = *(const uint2*)&sXp[(abase + lg + 16) * SH + cofs];
                    uint2 a11 = *(const uint2*)&sXp[(abase + lg + 24) * SH + cofs];
                    #pragma unroll
                    for (int nt = 0; nt < 4; nt++) {
                        uint2 bv = __ldg(wF2 + (s2 * 4 + nt) * 32 + lane);
                        mma_f16(acc[0][nt], a00.x, a01.x, a00.y, a01.y, bv.x, bv.y);
                        mma_f16(acc[1][nt], a10.x, a11.x, a10.y, a11.y, bv.x, bv.y);
                    }
                }
            }
        }
    }

    // epilogue: frags(+bias) -> smem [oc][px] -> coalesced g_offT stores
    float* sOut = (float*)smo;
    __syncthreads();
    #pragma unroll
    for (int mt = 0; mt < 2; mt++) {
        int px0 = warp_m * 32 + mt * 16 + lg;
        #pragma unroll
        for (int nt = 0; nt < 4; nt++) {
            int oc = warp_n * 32 + nt * 8 + 2 * le;
            float b0 = (oc < NOFF)     ? __ldg(&boff[oc])     : 0.f;
            float b1 = (oc + 1 < NOFF) ? __ldg(&boff[oc + 1]) : 0.f;
            sOut[oc * TPX + px0]           = acc[mt][nt][0] + b0;
            sOut[(oc + 1) * TPX + px0]     = acc[mt][nt][1] + b1;
            sOut[oc * TPX + px0 + 8]       = acc[mt][nt][2] + b0;
            sOut[(oc + 1) * TPX + px0 + 8] = acc[mt][nt][3] + b1;
        }
    }
    __syncthreads();
    {
        int oc = tid >> 2;
        int f0 = tid & 3;
        if (oc < NOFF) {
            float4* op = (float4*)(g_offT + ((size_t)bh * NOFF + oc) * WW + w0);
            const float4* sp = (const float4*)(sOut + oc * TPX);
            #pragma unroll
            for (int j = 0; j < 8; j++) op[f0 + j * 4] = sp[f0 + j * 4];
        }
    }
}

// ---------------- 4) main: MLP-pipelined fp16 gather + fp16 mma ---------------
// smem: sS 2*128*SH halves (36864B) + sG 2*128*8 floats (8192B) = 45056B
#define SMF_G   ((2 * TPX * SH * 2) / 4)
#define SM_TOTAL (2 * TPX * SH * 2 + 2 * TPX * 8 * 4)

__global__ __launch_bounds__(256, 2)
void main_kernel(float* __restrict__ out) {
    extern __shared__ float sm[];
    float* sG = sm + SMF_G;

    int bh = blockIdx.y;
    int b  = bh / HH, h = bh % HH;
    int w0 = blockIdx.x * TPX;
    int tid = threadIdx.x;
    int lane = tid & 31, wid = tid >> 5;

    int grp = tid >> 3;           // gather group 0..31 (4 px each)
    int f   = tid & 7;            // 16B fp16 chunk lane (positions 8f..8f+7)
    int warp_m = wid >> 1;
    int warp_n = wid & 1;
    int lg = lane >> 2;
    int le = lane & 3;

    const char*  xTb  = (const char*)(g_xT + (size_t)b * HH * WW * CC);
    const float* offb = g_offT + (size_t)bh * NOFF * WW + w0;

    float acc[2][4][4];
    #pragma unroll
    for (int mt = 0; mt < 2; mt++)
        #pragma unroll
        for (int nt = 0; nt < 4; nt++)
            #pragma unroll
            for (int e = 0; e < 4; e++) acc[mt][nt][e] = 0.f;

    auto setup = [&](int tap, int buf) {
        if (tid < TPX) {
            int px = tid;
            int i = tap / KK, k = tap - i * KK;
            int d = 1 << i;
            float dy = __ldg(offb + (size_t)(i * 18 + 2 * k) * WW + px);
            float dx = __ldg(offb + (size_t)(i * 18 + 2 * k + 1) * WW + px);
            float ys  = (float)h + (float)((k / 3 - 1) * d) + dy;
            float xsf = (float)(w0 + px) + (float)((k % 3 - 1) * d) + dx;
            float y0f = floorf(ys), x0f = floorf(xsf);
            float wy1 = ys - y0f, wx1 = xsf - x0f, wy0 = 1.f - wy1, wx0 = 1.f - wx1;
            float y1f = y0f + 1.f, x1f = x0f + 1.f;
            float vy0 = (y0f >= 0.f && y0f <= 255.f) ? 1.f : 0.f;
            float vy1 = (y1f >= 0.f && y1f <= 255.f) ? 1.f : 0.f;
            float vx0 = (x0f >= 0.f && x0f <= 255.f) ? 1.f : 0.f;
            float vx1 = (x1f >= 0.f && x1f <= 255.f) ? 1.f : 0.f;
            u32 iy0 = (u32)(int)fminf(fmaxf(y0f, 0.f), 255.f);
            u32 iy1 = (u32)(int)fminf(fmaxf(y1f, 0.f), 255.f);
            u32 ix0 = (u32)(int)fminf(fmaxf(x0f, 0.f), 255.f);
            u32 ix1 = (u32)(int)fminf(fmaxf(x1f, 0.f), 255.f);
            uint4 o;
            o.x = ((iy0 * WW + ix0) * CC) * 2u;   // BYTE offsets (fp16)
            o.y = ((iy0 * WW + ix1) * CC) * 2u;
            o.z = ((iy1 * WW + ix0) * CC) * 2u;
            o.w = ((iy1 * WW + ix1) * CC) * 2u;
            float4 cw = make_float4(wy0 * wx0 * vy0 * vx0, wy0 * wx1 * vy0 * vx1,
                                    wy1 * wx0 * vy1 * vx0, wy1 * wx1 * vy1 * vx1);
            *(uint4*) &sG[(buf * TPX + px) * 8]     = o;
            *(float4*)&sG[(buf * TPX + px) * 8 + 4] = cw;
        }
    };

    setup(0, 0);
    __syncthreads();

    for (int tap = 0; tap < ND * KK; tap++) {
        int p = tap & 1;
        __half* sS16 = (__half*)sm + p * (TPX * SH);

        // ---- gather tap -> sS[p]: 4 px per group, distance-2 MLP pipeline ----
        {
            const float* gbase = &sG[(p * TPX + grp * 4) * 8];

            float4 cwb[2];
            uint4  da[2], db[2], dc[2], dd[2];

            // issue loads for px slots 0 and 1 FIRST (max in-flight)
            {
                uint4 o0 = *(const uint4*)(gbase);
                cwb[0]   = *(const float4*)(gbase + 4);
                da[0] = __ldg((const uint4*)(xTb + o0.x) + f);
                db[0] = __ldg((const uint4*)(xTb + o0.y) + f);
                dc[0] = __ldg((const uint4*)(xTb + o0.z) + f);
                dd[0] = __ldg((const uint4*)(xTb + o0.w) + f);
                uint4 o1 = *(const uint4*)(gbase + 8);
                cwb[1]   = *(const float4*)(gbase + 12);
                da[1] = __ldg((const uint4*)(xTb + o1.x) + f);
                db[1] = __ldg((const uint4*)(xTb + o1.y) + f);
                dc[1] = __ldg((const uint4*)(xTb + o1.z) + f);
                dd[1] = __ldg((const uint4*)(xTb + o1.w) + f);
            }

            // independent work to cover initial latency: stage next tap's setup
            if (tap + 1 < ND * KK) setup(tap + 1, 1 - p);

            #pragma unroll
            for (int j = 0; j < 4; j++) {
                int sl = j & 1;
                float4 cw = cwb[sl];
                uint4 A = da[sl], B = db[sl], C = dc[sl], D = dd[sl];

                // reload this slot for px j+2 (consumed 2 combines later)
                if (j < 2) {
                    uint4 on = *(const uint4*)(gbase + (j + 2) * 8);
                    cwb[sl]  = *(const float4*)(gbase + (j + 2) * 8 + 4);
                    da[sl] = __ldg((const uint4*)(xTb + on.x) + f);
                    db[sl] = __ldg((const uint4*)(xTb + on.y) + f);
                    dc[sl] = __ldg((const uint4*)(xTb + on.z) + f);
                    dd[sl] = __ldg((const uint4*)(xTb + on.w) + f);
                }

                // combine 8 halves (positions 8f..8f+7) for pixel grp*4+j
                const __half2* ha = (const __half2*)&A;
                const __half2* hb = (const __half2*)&B;
                const __half2* hc = (const __half2*)&C;
                const __half2* hd = (const __half2*)&D;
                u32 outw[4];
                #pragma unroll
                for (int m = 0; m < 4; m++) {
                    float2 va = __half22float2(ha[m]);
                    float2 vb = __half22float2(hb[m]);
                    float2 vc = __half22float2(hc[m]);
                    float2 vd = __half22float2(hd[m]);
                    float r0 = cw.x * va.x + cw.y * vb.x + cw.z * vc.x + cw.w * vd.x;
                    float r1 = cw.x * va.y + cw.y * vb.y + cw.z * vc.y + cw.w * vd.y;
                    __half2 hr = __floats2half2_rn(r0, r1);
                    outw[m] = *(u32*)&hr;
                }
                *(uint4*)&sS16[(grp * 4 + j) * SH + 8 * f] =
                    make_uint4(outw[0], outw[1], outw[2], outw[3]);
            }
        }

        __syncthreads();   // sS[p] + sG[1-p] visible; only sync this tap

        // ---- einsum: A uint2 LDS from sS[p], B uint2 LDG (L1-hit), fp16 HMMA --
        {
            const uint2* wF2 = (const uint2*)g_weffH + (size_t)tap * 1024 + warp_n * 512;
            int arow = warp_m * 32 + lg;
            #pragma unroll
            for (int s2 = 0; s2 < 4; s2++) {
                int cofs = s2 * 16 + le * 4;
                uint2 a00 = *(const uint2*)&sS16[(arow)      * SH + cofs];
                uint2 a01 = *(const uint2*)&sS16[(arow + 8)  * SH + cofs];
                uint2 a10 = *(const uint2*)&sS16[(arow + 16) * SH + cofs];
                uint2 a11 = *(const uint2*)&sS16[(arow + 24) * SH + cofs];
                #pragma unroll
                for (int nt = 0; nt < 4; nt++) {
                    uint2 bv = __ldg(wF2 + (s2 * 4 + nt) * 32 + lane);
                    mma_f16(acc[0][nt], a00.x, a01.x, a00.y, a01.y, bv.x, bv.y);
                    mma_f16(acc[1][nt], a10.x, a11.x, a10.y, a11.y, bv.x, bv.y);
                }
            }
        }
        // no trailing sync: next gather targets the other sS buffer
    }

    // epilogue: frags -> smem [oo][px] -> coalesced stores
    __syncthreads();
    float* sOut = sm;
    #pragma unroll
    for (int mt = 0; mt < 2; mt++) {
        int px0 = warp_m * 32 + mt * 16 + lg;
        #pragma unroll
        for (int nt = 0; nt < 4; nt++) {
            int oo = warp_n * 32 + nt * 8 + 2 * le;
            sOut[oo * TPX + px0]           = acc[mt][nt][0];
            sOut[(oo + 1) * TPX + px0]     = acc[mt][nt][1];
            sOut[oo * TPX + px0 + 8]       = acc[mt][nt][2];
            sOut[(oo + 1) * TPX + px0 + 8] = acc[mt][nt][3];
        }
    }
    __syncthreads();
    {
        int row = tid >> 2;
        int f0  = tid & 3;
        float4* op = (float4*)(out + (((size_t)(b * CC + row) * HH + h) * WW + w0));
        const float4* sp = (const float4*)(sOut + row * TPX);
        #pragma unroll
        for (int j = 0; j < 8; j++) op[f0 + j * 4] = sp[f0 + j * 4];
    }
}

// ---------------- launch ------------------------------------------------------
extern "C" void kernel_launch(void* const* d_in, const int* in_sizes, int n_in,
                              void* d_out, int out_size) {
    const float* x     = (const float*)d_in[0];
    const float* Woff  = (const float*)d_in[1];
    const float* boff  = (const float*)d_in[2];
    const float* Wd    = (const float*)d_in[3];
    const float* Wfuse = (const float*)d_in[4];
    float* out = (float*)d_out;

    int smem_main = SM_TOTAL;                 // 45056
    int smem_off  = 2 * 130 * SH * 2;         // 37440
    static int smem_set = 0;
    if (!smem_set) {
        cudaFuncSetAttribute(main_kernel,
                             cudaFuncAttributeMaxDynamicSharedMemorySize, smem_main);
        cudaFuncSetAttribute(offconv_kernel,
                             cudaFuncAttributeMaxDynamicSharedMemorySize, smem_off);
        smem_set = 1;
    }

    transpose_kernel<<<dim3(WW / 32, CC / 32, BB * HH), dim3(32, 8)>>>(x);
    weff_kernel<<<(ND * KK * CC * CC + 255) / 256, 256>>>(Wd, Wfuse);
    woff_kernel<<<(KK * CC * CC + 255) / 256, 256>>>(Woff);
    offconv_kernel<<<dim3(WW / TPX, BB * HH), 256, smem_off>>>(boff);
    main_kernel<<<dim3(WW / TPX, BB * HH), 256, smem_main>>>(out);
}

// round 13
// speedup vs baseline: 1.9535x; 1.0260x over previous
#include <cuda_runtime.h>
#include <cuda_fp16.h>
#include <cstdint>

#define BB   2
#define CC   64
#define HH   256
#define WW   256
#define KK   9
#define ND   3
#define NTAP 27
#define NOFF 54
#define TPX  128         // pixels per main-kernel block
#define SH   72          // sS row stride in halves (64 + 8 pad = 144B)

typedef unsigned long long ull;
typedef unsigned int u32;

#define BAR_SYNC(id, cnt)   asm volatile("bar.sync %0, %1;"   :: "r"(id), "r"(cnt) : "memory")
#define BAR_ARRIVE(id, cnt) asm volatile("bar.arrive %0, %1;" :: "r"(id), "r"(cnt) : "memory")
// named barrier ids
#define BAR_FULL0  1
#define BAR_FULL1  2
#define BAR_EMPTY0 3
#define BAR_EMPTY1 4
#define BAR_PROD   5
#define BAR_CONS   6

// m16n8k16 fp16 mma, fp32 accumulate (sm_80 baseline PTX -> HMMA on sm_103)
__device__ __forceinline__ void mma_f16(float* c,
                                        u32 a0, u32 a1, u32 a2, u32 a3,
                                        u32 b0, u32 b1) {
    asm("mma.sync.aligned.m16n8k16.row.col.f32.f16.f16.f32 "
        "{%0,%1,%2,%3}, {%4,%5,%6,%7}, {%8,%9}, {%0,%1,%2,%3};"
        : "+f"(c[0]), "+f"(c[1]), "+f"(c[2]), "+f"(c[3])
        : "r"(a0), "r"(a1), "r"(a2), "r"(a3), "r"(b0), "r"(b1));
}

// ---------------- scratch ----------------------------------------------------
__device__ __half g_xT[(size_t)BB * HH * WW * CC];         // fp16, P(c)-ordered NHWC
__device__ float  g_offT[(size_t)BB * HH * NOFF * WW];     // offsets (bh, ch, w)
__device__ __half g_weffH[(size_t)ND * KK * CC * CC];      // frag-ordered fp16
__device__ __half g_woffH[(size_t)KK * CC * CC];           // offset-conv weights

__device__ __forceinline__ int P_of(int c) {
    return (c >> 4) * 16 + ((c & 7) >> 1) * 4 + ((c >> 3) & 1) * 2 + (c & 1);
}
__device__ __forceinline__ int frag_index_h(int oo, int c) {
    int s = c >> 4, r = c & 15;
    int le = (r & 7) >> 1, hidx = ((r >> 3) << 1) | (r & 1);
    int wn = oo >> 5, nt = (oo >> 3) & 3, g = oo & 7;
    return ((((wn * 4 + s) * 4 + nt) * 32) + g * 4 + le) * 4 + hidx;
}

// ---------------- 1) transpose x -> fragment-ordered fp16 NHWC ----------------
__global__ void transpose_kernel(const float* __restrict__ x) {
    __shared__ float tile[32][33];
    int bh = blockIdx.z;
    int b  = bh / HH, h = bh % HH;
    int w0 = blockIdx.x * 32;
    int c0 = blockIdx.y * 32;
    int tx = threadIdx.x, ty = threadIdx.y;

    #pragma unroll
    for (int j = 0; j < 4; j++) {
        int c = c0 + ty + j * 8;
        tile[ty + j * 8][tx] = x[(((size_t)b * CC + c) * HH + h) * WW + (w0 + tx)];
    }
    __syncthreads();
    #pragma unroll
    for (int j = 0; j < 4; j++) {
        int w = w0 + ty + j * 8;
        int c = c0 + tx;
        g_xT[(((size_t)b * HH + h) * WW + w) * CC + P_of(c)] =
            __float2half(tile[tx][ty + j * 8]);
    }
}

// ---------------- 2a) Weff -> fragment-ordered fp16 ---------------------------
__global__ void weff_kernel(const float* __restrict__ Wd,
                            const float* __restrict__ Wfuse) {
    int idx = blockIdx.x * 256 + threadIdx.x;
    if (idx >= ND * KK * CC * CC) return;
    int oo = idx % CC;
    int c  = (idx / CC) % CC;
    int k  = (idx / (CC * CC)) % KK;
    int i  = idx / (CC * CC * KK);
    float acc = 0.f;
    #pragma unroll 8
    for (int o = 0; o < CC; o++) {
        acc = fmaf(Wfuse[oo * (ND * CC) + i * CC + o],
                   Wd[(((size_t)(i * CC + o) * CC + c) * KK) + k], acc);
    }
    int tap = i * KK + k;
    g_weffH[(size_t)tap * CC * CC + frag_index_h(oo, c)] = __float2half(acc);
}

// ---------------- 2b) Woff -> fragment-ordered fp16 ---------------------------
__global__ void woff_kernel(const float* __restrict__ Woff) {
    int idx = blockIdx.x * 256 + threadIdx.x;
    if (idx >= KK * CC * CC) return;
    int c  = idx % CC;
    int oc = (idx / CC) % CC;
    int k  = idx / (CC * CC);
    float v = (oc < NOFF) ? Woff[(size_t)oc * CC * KK + c * KK + k] : 0.f;
    g_woffH[(size_t)k * CC * CC + frag_index_h(oc, c)] = __float2half(v);
}

// ---------------- 3) offset conv via fp16 mma, 1 sync per ky -------------------
__global__ __launch_bounds__(256, 2)
void offconv_kernel(const float* __restrict__ boff) {
    extern __shared__ u32 smo[];
    __half* sX = (__half*)smo;

    int bh = blockIdx.y;
    int b  = bh / HH, h = bh % HH;
    int w0 = blockIdx.x * TPX;
    int tid = threadIdx.x;
    int lane = tid & 31, wid = tid >> 5;
    int warp_m = wid >> 1;
    int warp_n = wid & 1;
    int lg = lane >> 2;
    int le = lane & 3;

    const __half* xTrow = g_xT + (size_t)b * HH * WW * CC;

    float acc[2][4][4];
    #pragma unroll
    for (int mt = 0; mt < 2; mt++)
        #pragma unroll
        for (int nt = 0; nt < 4; nt++)
            #pragma unroll
            for (int e = 0; e < 4; e++) acc[mt][nt][e] = 0.f;

    for (int ky = 0; ky < 3; ky++) {
        int row = h + ky - 1;
        bool valid = (row >= 0 && row < HH);
        __half* sXp = sX + (ky & 1) * (130 * SH);

        if (valid) {
            const uint4* src = (const uint4*)(xTrow + (size_t)row * WW * CC);
            for (int t = tid; t < 130 * 8; t += 256) {
                int px = t >> 3, ch = t & 7;
                int w = w0 - 1 + px;
                uint4 val = make_uint4(0u, 0u, 0u, 0u);
                if (w >= 0 && w < WW) val = __ldg(src + (size_t)w * 8 + ch);
                *(uint4*)&sXp[px * SH + ch * 8] = val;
            }
        }
        __syncthreads();

        if (valid) {
            #pragma unroll
            for (int kx = 0; kx < 3; kx++) {
                int k = ky * 3 + kx;
                const uint2* wF2 = (const uint2*)g_woffH + (size_t)k * 1024 + warp_n * 512;
                int abase = warp_m * 32 + kx;
                #pragma unroll
                for (int s2 = 0; s2 < 4; s2++) {
                    int cofs = s2 * 16 + le * 4;
                    uint2 a00 = *(const uint2*)&sXp[(abase + lg)      * SH + cofs];
                    uint2 a01 = *(const uint2*)&sXp[(abase + lg + 8)  * SH + cofs];
                    uint2 a10 = *(const uint2*)&sXp[(abase + lg + 16) * SH + cofs];
                    uint2 a11 = *(const uint2*)&sXp[(abase + lg + 24) * SH + cofs];
                    #pragma unroll
                    for (int nt = 0; nt < 4; nt++) {
                        uint2 bv = __ldg(wF2 + (s2 * 4 + nt) * 32 + lane);
                        mma_f16(acc[0][nt], a00.x, a01.x, a00.y, a01.y, bv.x, bv.y);
                        mma_f16(acc[1][nt], a10.x, a11.x, a10.y, a11.y, bv.x, bv.y);
                    }
                }
            }
        }
    }

    float* sOut = (float*)smo;
    __syncthreads();
    #pragma unroll
    for (int mt = 0; mt < 2; mt++) {
        int px0 = warp_m * 32 + mt * 16 + lg;
        #pragma unroll
        for (int nt = 0; nt < 4; nt++) {
            int oc = warp_n * 32 + nt * 8 + 2 * le;
            float b0 = (oc < NOFF)     ? __ldg(&boff[oc])     : 0.f;
            float b1 = (oc + 1 < NOFF) ? __ldg(&boff[oc + 1]) : 0.f;
            sOut[oc * TPX + px0]           = acc[mt][nt][0] + b0;
            sOut[(oc + 1) * TPX + px0]     = acc[mt][nt][1] + b1;
            sOut[oc * TPX + px0 + 8]       = acc[mt][nt][2] + b0;
            sOut[(oc + 1) * TPX + px0 + 8] = acc[mt][nt][3] + b1;
        }
    }
    __syncthreads();
    {
        int oc = tid >> 2;
        int f0 = tid & 3;
        if (oc < NOFF) {
            float4* op = (float4*)(g_offT + ((size_t)bh * NOFF + oc) * WW + w0);
            const float4* sp = (const float4*)(sOut + oc * TPX);
            #pragma unroll
            for (int j = 0; j < 8; j++) op[f0 + j * 4] = sp[f0 + j * 4];
        }
    }
}

// ---------------- 4) main: WARP-SPECIALIZED producer/consumer -----------------
// warps 0-3 (tid<128): gather producers. warps 4-7: mma consumers.
// smem: sS 2*128*SH halves (36864B) + sG 2*128*8 floats (8192B) = 45056B
#define SMF_G   ((2 * TPX * SH * 2) / 4)
#define SM_TOTAL (2 * TPX * SH * 2 + 2 * TPX * 8 * 4)

__global__ __launch_bounds__(256, 2)
void main_kernel(float* __restrict__ out) {
    extern __shared__ float sm[];
    float* sG = sm + SMF_G;

    int bh = blockIdx.y;
    int b  = bh / HH, h = bh % HH;
    int w0 = blockIdx.x * TPX;
    int tid = threadIdx.x;
    int lane = tid & 31, wid = tid >> 5;

    const char*  xTb  = (const char*)(g_xT + (size_t)b * HH * WW * CC);
    const float* offb = g_offT + (size_t)bh * NOFF * WW + w0;

    if (tid < 128) {
        // ===================== PRODUCER (warps 0-3) ==========================
        int grp = tid >> 3;       // 16 groups, 8 px each
        int f   = tid & 7;        // 16B fp16 chunk lane

        // per-pixel bilinear setup (tid 0..127 == px 0..127)
        auto setup = [&](int tap, int buf) {
            int px = tid;
            int i = tap / KK, k = tap - i * KK;
            int d = 1 << i;
            float dy = __ldg(offb + (size_t)(i * 18 + 2 * k) * WW + px);
            float dx = __ldg(offb + (size_t)(i * 18 + 2 * k + 1) * WW + px);
            float ys  = (float)h + (float)((k / 3 - 1) * d) + dy;
            float xsf = (float)(w0 + px) + (float)((k % 3 - 1) * d) + dx;
            float y0f = floorf(ys), x0f = floorf(xsf);
            float wy1 = ys - y0f, wx1 = xsf - x0f, wy0 = 1.f - wy1, wx0 = 1.f - wx1;
            float y1f = y0f + 1.f, x1f = x0f + 1.f;
            float vy0 = (y0f >= 0.f && y0f <= 255.f) ? 1.f : 0.f;
            float vy1 = (y1f >= 0.f && y1f <= 255.f) ? 1.f : 0.f;
            float vx0 = (x0f >= 0.f && x0f <= 255.f) ? 1.f : 0.f;
            float vx1 = (x1f >= 0.f && x1f <= 255.f) ? 1.f : 0.f;
            u32 iy0 = (u32)(int)fminf(fmaxf(y0f, 0.f), 255.f);
            u32 iy1 = (u32)(int)fminf(fmaxf(y1f, 0.f), 255.f);
            u32 ix0 = (u32)(int)fminf(fmaxf(x0f, 0.f), 255.f);
            u32 ix1 = (u32)(int)fminf(fmaxf(x1f, 0.f), 255.f);
            uint4 o;
            o.x = ((iy0 * WW + ix0) * CC) * 2u;
            o.y = ((iy0 * WW + ix1) * CC) * 2u;
            o.z = ((iy1 * WW + ix0) * CC) * 2u;
            o.w = ((iy1 * WW + ix1) * CC) * 2u;
            float4 cw = make_float4(wy0 * wx0 * vy0 * vx0, wy0 * wx1 * vy0 * vx1,
                                    wy1 * wx0 * vy1 * vx0, wy1 * wx1 * vy1 * vx1);
            *(uint4*) &sG[(buf * TPX + px) * 8]     = o;
            *(float4*)&sG[(buf * TPX + px) * 8 + 4] = cw;
        };

        setup(0, 0);
        BAR_SYNC(BAR_PROD, 128);

        for (int tap = 0; tap < NTAP; tap++) {
            int p = tap & 1;
            __half* sS16 = (__half*)sm + p * (TPX * SH);
            const float* gbase = &sG[(p * TPX + grp * 8) * 8];

            // 1) issue slot0/slot1 loads (register targets; legal before EMPTY)
            float4 cwb[2];
            uint4  da[2], db[2], dc[2], dd[2];
            {
                uint4 o0 = *(const uint4*)(gbase);
                cwb[0]   = *(const float4*)(gbase + 4);
                da[0] = __ldg((const uint4*)(xTb + o0.x) + f);
                db[0] = __ldg((const uint4*)(xTb + o0.y) + f);
                dc[0] = __ldg((const uint4*)(xTb + o0.z) + f);
                dd[0] = __ldg((const uint4*)(xTb + o0.w) + f);
                uint4 o1 = *(const uint4*)(gbase + 8);
                cwb[1]   = *(const float4*)(gbase + 12);
                da[1] = __ldg((const uint4*)(xTb + o1.x) + f);
                db[1] = __ldg((const uint4*)(xTb + o1.y) + f);
                dc[1] = __ldg((const uint4*)(xTb + o1.z) + f);
                dd[1] = __ldg((const uint4*)(xTb + o1.w) + f);
            }

            // 2) stage next tap's setup into sG[1-p] (consumers never touch sG)
            if (tap + 1 < NTAP) setup(tap + 1, 1 - p);

            // 3) wait for consumers to be done with buffer p (taps >= 2)
            if (tap >= 2) BAR_SYNC((p ? BAR_EMPTY1 : BAR_EMPTY0), 256);

            // 4) combine + STS with distance-2 reload pipeline over 8 px
            #pragma unroll
            for (int j = 0; j < 8; j++) {
                int sl = j & 1;
                float4 cw = cwb[sl];
                uint4 A = da[sl], B = db[sl], C = dc[sl], D = dd[sl];

                if (j < 6) {
                    uint4 on = *(const uint4*)(gbase + (j + 2) * 8);
                    cwb[sl]  = *(const float4*)(gbase + (j + 2) * 8 + 4);
                    da[sl] = __ldg((const uint4*)(xTb + on.x) + f);
                    db[sl] = __ldg((const uint4*)(xTb + on.y) + f);
                    dc[sl] = __ldg((const uint4*)(xTb + on.z) + f);
                    dd[sl] = __ldg((const uint4*)(xTb + on.w) + f);
                }

                const __half2* ha = (const __half2*)&A;
                const __half2* hb = (const __half2*)&B;
                const __half2* hc = (const __half2*)&C;
                const __half2* hd = (const __half2*)&D;
                u32 outw[4];
                #pragma unroll
                for (int m = 0; m < 4; m++) {
                    float2 va = __half22float2(ha[m]);
                    float2 vb = __half22float2(hb[m]);
                    float2 vc = __half22float2(hc[m]);
                    float2 vd = __half22float2(hd[m]);
                    float r0 = cw.x * va.x + cw.y * vb.x + cw.z * vc.x + cw.w * vd.x;
                    float r1 = cw.x * va.y + cw.y * vb.y + cw.z * vc.y + cw.w * vd.y;
                    __half2 hr = __floats2half2_rn(r0, r1);
                    outw[m] = *(u32*)&hr;
                }
                *(uint4*)&sS16[(grp * 8 + j) * SH + 8 * f] =
                    make_uint4(outw[0], outw[1], outw[2], outw[3]);
            }

            // 5) publish buffer p; 6) producer-only fence for sG[1-p]
            BAR_ARRIVE((p ? BAR_FULL1 : BAR_FULL0), 256);
            BAR_SYNC(BAR_PROD, 128);
        }
    } else {
        // ===================== CONSUMER (warps 4-7) ==========================
        int cwarp = wid - 4;          // 0..3, 32 px each; all 64 oo
        int lg = lane >> 2;
        int le = lane & 3;
        int arow = cwarp * 32 + lg;

        float acc[2][8][4];
        #pragma unroll
        for (int mt = 0; mt < 2; mt++)
            #pragma unroll
            for (int nt = 0; nt < 8; nt++)
                #pragma unroll
                for (int e = 0; e < 4; e++) acc[mt][nt][e] = 0.f;

        for (int tap = 0; tap < NTAP; tap++) {
            int p = tap & 1;
            __half* sS16 = (__half*)sm + p * (TPX * SH);

            BAR_SYNC((p ? BAR_FULL1 : BAR_FULL0), 256);

            const uint2* wB = (const uint2*)g_weffH + (size_t)tap * 1024;
            #pragma unroll
            for (int s2 = 0; s2 < 4; s2++) {
                int cofs = s2 * 16 + le * 4;
                uint2 a00 = *(const uint2*)&sS16[(arow)      * SH + cofs];
                uint2 a01 = *(const uint2*)&sS16[(arow + 8)  * SH + cofs];
                uint2 a10 = *(const uint2*)&sS16[(arow + 16) * SH + cofs];
                uint2 a11 = *(const uint2*)&sS16[(arow + 24) * SH + cofs];
                #pragma unroll
                for (int nt2 = 0; nt2 < 8; nt2++) {
                    int bidx = (((nt2 >> 2) * 4 + s2) * 4 + (nt2 & 3)) * 32 + lane;
                    uint2 bv = __ldg(wB + bidx);
                    mma_f16(acc[0][nt2], a00.x, a01.x, a00.y, a01.y, bv.x, bv.y);
                    mma_f16(acc[1][nt2], a10.x, a11.x, a10.y, a11.y, bv.x, bv.y);
                }
            }

            if (tap + 2 < NTAP)
                BAR_ARRIVE((p ? BAR_EMPTY1 : BAR_EMPTY0), 256);
        }

        // consumer-only fence: all mma reads done before sOut overwrites sS
        BAR_SYNC(BAR_CONS, 128);

        float* sOut = sm;     // 64 oo x 128 px floats (32KB, inside sS region)
        #pragma unroll
        for (int mt = 0; mt < 2; mt++) {
            int px0 = cwarp * 32 + mt * 16 + lg;
            #pragma unroll
            for (int nt2 = 0; nt2 < 8; nt2++) {
                int oo = (nt2 >> 2) * 32 + (nt2 & 3) * 8 + 2 * le;
                sOut[oo * TPX + px0]           = acc[mt][nt2][0];
                sOut[(oo + 1) * TPX + px0]     = acc[mt][nt2][1];
                sOut[oo * TPX + px0 + 8]       = acc[mt][nt2][2];
                sOut[(oo + 1) * TPX + px0 + 8] = acc[mt][nt2][3];
            }
        }
    }

    // all 256 threads: wait for sOut, then coalesced stores
    __syncthreads();
    {
        float* sOut = sm;
        int row = tid >> 2;
        int f0  = tid & 3;
        float4* op = (float4*)(out + (((size_t)(b * CC + row) * HH + h) * WW + w0));
        const float4* sp = (const float4*)(sOut + row * TPX);
        #pragma unroll
        for (int j = 0; j < 8; j++) op[f0 + j * 4] = sp[f0 + j * 4];
    }
}

// ---------------- launch ------------------------------------------------------
extern "C" void kernel_launch(void* const* d_in, const int* in_sizes, int n_in,
                              void* d_out, int out_size) {
    const float* x     = (const float*)d_in[0];
    const float* Woff  = (const float*)d_in[1];
    const float* boff  = (const float*)d_in[2];
    const float* Wd    = (const float*)d_in[3];
    const float* Wfuse = (const float*)d_in[4];
    float* out = (float*)d_out;

    int smem_main = SM_TOTAL;                 // 45056
    int smem_off  = 2 * 130 * SH * 2;         // 37440
    static int smem_set = 0;
    if (!smem_set) {
        cudaFuncSetAttribute(main_kernel,
                             cudaFuncAttributeMaxDynamicSharedMemorySize, smem_main);
        cudaFuncSetAttribute(offconv_kernel,
                             cudaFuncAttributeMaxDynamicSharedMemorySize, smem_off);
        smem_set = 1;
    }

    transpose_kernel<<<dim3(WW / 32, CC / 32, BB * HH), dim3(32, 8)>>>(x);
    weff_kernel<<<(ND * KK * CC * CC + 255) / 256, 256>>>(Wd, Wfuse);
    woff_kernel<<<(KK * CC * CC + 255) / 256, 256>>>(Woff);
    offconv_kernel<<<dim3(WW / TPX, BB * HH), 256, smem_off>>>(boff);
    main_kernel<<<dim3(WW / TPX, BB * HH), 256, smem_main>>>(out);
}

// round 14
// speedup vs baseline: 1.9925x; 1.0200x over previous
#include <cuda_runtime.h>
#include <cuda_fp16.h>
#include <cstdint>

#define BB   2
#define CC   64
#define HH   256
#define WW   256
#define KK   9
#define ND   3
#define NTAP 27
#define NOFF 54
#define TPX  128         // pixels per main-kernel block

typedef unsigned long long ull;
typedef unsigned int u32;

#define BAR_SYNC(id, cnt)   asm volatile("bar.sync %0, %1;"   :: "r"(id), "r"(cnt) : "memory")
#define BAR_ARRIVE(id, cnt) asm volatile("bar.arrive %0, %1;" :: "r"(id), "r"(cnt) : "memory")
#define BAR_FULL0  1
#define BAR_FULL1  2
#define BAR_EMPTY0 3
#define BAR_EMPTY1 4
#define BAR_PROD   5
#define BAR_CONS   6

#define FMA2(d, a, b, c) asm("fma.rn.f32x2 %0, %1, %2, %3;" : "=l"(d) : "l"(a), "l"(b), "l"(c))
#define PACK2(d, lo, hi) asm("mov.b64 %0, {%1, %2};" : "=l"(d) : "f"(lo), "f"(hi))
#define UNPACK2(lo, hi, s) asm("mov.b64 {%0, %1}, %2;" : "=f"(lo), "=f"(hi) : "l"(s))

// m16n8k16 fp16 mma, fp32 accumulate (sm_80 baseline PTX -> HMMA on sm_103)
__device__ __forceinline__ void mma_f16(float* c,
                                        u32 a0, u32 a1, u32 a2, u32 a3,
                                        u32 b0, u32 b1) {
    asm("mma.sync.aligned.m16n8k16.row.col.f32.f16.f16.f32 "
        "{%0,%1,%2,%3}, {%4,%5,%6,%7}, {%8,%9}, {%0,%1,%2,%3};"
        : "+f"(c[0]), "+f"(c[1]), "+f"(c[2]), "+f"(c[3])
        : "r"(a0), "r"(a1), "r"(a2), "r"(a3), "r"(b0), "r"(b1));
}

// ---------------- scratch ----------------------------------------------------
__device__ __half g_xT[(size_t)BB * HH * WW * CC];         // fp16, P(c)-ordered NHWC
__device__ float  g_offT[(size_t)BB * HH * NOFF * WW];     // offsets (bh, ch, w)
__device__ __half g_weffH[(size_t)ND * KK * CC * CC];      // frag-ordered fp16
__device__ __half g_woffH[(size_t)KK * CC * CC];           // offset-conv weights

__device__ __forceinline__ int P_of(int c) {
    return (c >> 4) * 16 + ((c & 7) >> 1) * 4 + ((c >> 3) & 1) * 2 + (c & 1);
}
__device__ __forceinline__ int frag_index_h(int oo, int c) {
    int s = c >> 4, r = c & 15;
    int le = (r & 7) >> 1, hidx = ((r >> 3) << 1) | (r & 1);
    int wn = oo >> 5, nt = (oo >> 3) & 3, g = oo & 7;
    return ((((wn * 4 + s) * 4 + nt) * 32) + g * 4 + le) * 4 + hidx;
}

// ---------------- 1) transpose x -> fragment-ordered fp16 NHWC ----------------
__global__ void transpose_kernel(const float* __restrict__ x) {
    __shared__ float tile[32][33];
    int bh = blockIdx.z;
    int b  = bh / HH, h = bh % HH;
    int w0 = blockIdx.x * 32;
    int c0 = blockIdx.y * 32;
    int tx = threadIdx.x, ty = threadIdx.y;

    #pragma unroll
    for (int j = 0; j < 4; j++) {
        int c = c0 + ty + j * 8;
        tile[ty + j * 8][tx] = x[(((size_t)b * CC + c) * HH + h) * WW + (w0 + tx)];
    }
    __syncthreads();
    #pragma unroll
    for (int j = 0; j < 4; j++) {
        int w = w0 + ty + j * 8;
        int c = c0 + tx;
        g_xT[(((size_t)b * HH + h) * WW + w) * CC + P_of(c)] =
            __float2half(tile[tx][ty + j * 8]);
    }
}

// ---------------- 2a) Weff -> fragment-ordered fp16 ---------------------------
__global__ void weff_kernel(const float* __restrict__ Wd,
                            const float* __restrict__ Wfuse) {
    int idx = blockIdx.x * 256 + threadIdx.x;
    if (idx >= ND * KK * CC * CC) return;
    int oo = idx % CC;
    int c  = (idx / CC) % CC;
    int k  = (idx / (CC * CC)) % KK;
    int i  = idx / (CC * CC * KK);
    float acc = 0.f;
    #pragma unroll 8
    for (int o = 0; o < CC; o++) {
        acc = fmaf(Wfuse[oo * (ND * CC) + i * CC + o],
                   Wd[(((size_t)(i * CC + o) * CC + c) * KK) + k], acc);
    }
    int tap = i * KK + k;
    g_weffH[(size_t)tap * CC * CC + frag_index_h(oo, c)] = __float2half(acc);
}

// ---------------- 2b) Woff -> fragment-ordered fp16 ---------------------------
__global__ void woff_kernel(const float* __restrict__ Woff) {
    int idx = blockIdx.x * 256 + threadIdx.x;
    if (idx >= KK * CC * CC) return;
    int c  = idx % CC;
    int oc = (idx / CC) % CC;
    int k  = idx / (CC * CC);
    float v = (oc < NOFF) ? Woff[(size_t)oc * CC * KK + c * KK + k] : 0.f;
    g_woffH[(size_t)k * CC * CC + frag_index_h(oc, c)] = __float2half(v);
}

// ---------------- 3) offset conv via fp16 mma, swizzled smem -------------------
// smem: sX[2][130*64] halves (33280B); epilogue sOut 64x128 f32 (32768B)
__global__ __launch_bounds__(256, 2)
void offconv_kernel(const float* __restrict__ boff) {
    extern __shared__ u32 smo[];
    __half* sX = (__half*)smo;

    int bh = blockIdx.y;
    int b  = bh / HH, h = bh % HH;
    int w0 = blockIdx.x * TPX;
    int tid = threadIdx.x;
    int lane = tid & 31, wid = tid >> 5;
    int warp_m = wid >> 1;
    int warp_n = wid & 1;
    int lg = lane >> 2;
    int le = lane & 3;

    const __half* xTrow = g_xT + (size_t)b * HH * WW * CC;

    float acc[2][4][4];
    #pragma unroll
    for (int mt = 0; mt < 2; mt++)
        #pragma unroll
        for (int nt = 0; nt < 4; nt++)
            #pragma unroll
            for (int e = 0; e < 4; e++) acc[mt][nt][e] = 0.f;

    for (int ky = 0; ky < 3; ky++) {
        int row = h + ky - 1;
        bool valid = (row >= 0 && row < HH);
        __half* sXp = sX + (ky & 1) * (130 * 64);

        if (valid) {
            const uint4* src = (const uint4*)(xTrow + (size_t)row * WW * CC);
            for (int t = tid; t < 130 * 8; t += 256) {
                int px = t >> 3, ch = t & 7;
                int w = w0 - 1 + px;
                uint4 val = make_uint4(0u, 0u, 0u, 0u);
                if (w >= 0 && w < WW) val = __ldg(src + (size_t)w * 8 + ch);
                *(uint4*)&sXp[px * 64 + 8 * (ch ^ (px & 7))] = val;
            }
        }
        __syncthreads();

        if (valid) {
            #pragma unroll
            for (int kx = 0; kx < 3; kx++) {
                int k = ky * 3 + kx;
                const uint2* wF2 = (const uint2*)g_woffH + (size_t)k * 1024 + warp_n * 512;
                int abase = warp_m * 32 + kx;
                int rs = (abase + lg) & 7;
                #pragma unroll
                for (int s2 = 0; s2 < 4; s2++) {
                    int sw = (((s2 << 1) + (le >> 1)) ^ rs) * 8 + (le & 1) * 4;
                    uint2 a00 = *(const uint2*)&sXp[(abase + lg)      * 64 + sw];
                    uint2 a01 = *(const uint2*)&sXp[(abase + lg + 8)  * 64 + sw];
                    uint2 a10 = *(const uint2*)&sXp[(abase + lg + 16) * 64 + sw];
                    uint2 a11 = *(const uint2*)&sXp[(abase + lg + 24) * 64 + sw];
                    #pragma unroll
                    for (int nt = 0; nt < 4; nt++) {
                        uint2 bv = __ldg(wF2 + (s2 * 4 + nt) * 32 + lane);
                        mma_f16(acc[0][nt], a00.x, a01.x, a00.y, a01.y, bv.x, bv.y);
                        mma_f16(acc[1][nt], a10.x, a11.x, a10.y, a11.y, bv.x, bv.y);
                    }
                }
            }
        }
    }

    float* sOut = (float*)smo;
    __syncthreads();
    #pragma unroll
    for (int mt = 0; mt < 2; mt++) {
        int px0 = warp_m * 32 + mt * 16 + lg;
        #pragma unroll
        for (int nt = 0; nt < 4; nt++) {
            int oc = warp_n * 32 + nt * 8 + 2 * le;
            float b0 = (oc < NOFF)     ? __ldg(&boff[oc])     : 0.f;
            float b1 = (oc + 1 < NOFF) ? __ldg(&boff[oc + 1]) : 0.f;
            sOut[oc * TPX + px0]           = acc[mt][nt][0] + b0;
            sOut[(oc + 1) * TPX + px0]     = acc[mt][nt][1] + b1;
            sOut[oc * TPX + px0 + 8]       = acc[mt][nt][2] + b0;
            sOut[(oc + 1) * TPX + px0 + 8] = acc[mt][nt][3] + b1;
        }
    }
    __syncthreads();
    {
        int oc = tid >> 2;
        int f0 = tid & 3;
        if (oc < NOFF) {
            float4* op = (float4*)(g_offT + ((size_t)bh * NOFF + oc) * WW + w0);
            const float4* sp = (const float4*)(sOut + oc * TPX);
            #pragma unroll
            for (int j = 0; j < 8; j++) op[f0 + j * 4] = sp[f0 + j * 4];
        }
    }
}

// ---------------- 4) main: warp-specialized, swizzled smem, FFMA2 --------------
// smem: sS 2*128*64 halves (32768B) + sG 2*128*8 floats (8192B) = 40960B
#define SMF_G   ((2 * TPX * 64 * 2) / 4)
#define SM_TOTAL (2 * TPX * 64 * 2 + 2 * TPX * 8 * 4)

__global__ __launch_bounds__(256, 2)
void main_kernel(float* __restrict__ out) {
    extern __shared__ float sm[];
    float* sG = sm + SMF_G;

    int bh = blockIdx.y;
    int b  = bh / HH, h = bh % HH;
    int w0 = blockIdx.x * TPX;
    int tid = threadIdx.x;
    int lane = tid & 31, wid = tid >> 5;

    const char*  xTb  = (const char*)(g_xT + (size_t)b * HH * WW * CC);
    const float* offb = g_offT + (size_t)bh * NOFF * WW + w0;

    if (tid < 128) {
        // ===================== PRODUCER (warps 0-3) ==========================
        int grp = tid >> 3;       // 16 groups, 8 px each
        int f   = tid & 7;        // 16B fp16 chunk lane

        auto setup = [&](int tap, int buf) {
            int px = tid;
            int i = tap / KK, k = tap - i * KK;
            int d = 1 << i;
            float dy = __ldg(offb + (size_t)(i * 18 + 2 * k) * WW + px);
            float dx = __ldg(offb + (size_t)(i * 18 + 2 * k + 1) * WW + px);
            float ys  = (float)h + (float)((k / 3 - 1) * d) + dy;
            float xsf = (float)(w0 + px) + (float)((k % 3 - 1) * d) + dx;
            float y0f = floorf(ys), x0f = floorf(xsf);
            float wy1 = ys - y0f, wx1 = xsf - x0f, wy0 = 1.f - wy1, wx0 = 1.f - wx1;
            float y1f = y0f + 1.f, x1f = x0f + 1.f;
            float vy0 = (y0f >= 0.f && y0f <= 255.f) ? 1.f : 0.f;
            float vy1 = (y1f >= 0.f && y1f <= 255.f) ? 1.f : 0.f;
            float vx0 = (x0f >= 0.f && x0f <= 255.f) ? 1.f : 0.f;
            float vx1 = (x1f >= 0.f && x1f <= 255.f) ? 1.f : 0.f;
            u32 iy0 = (u32)(int)fminf(fmaxf(y0f, 0.f), 255.f);
            u32 iy1 = (u32)(int)fminf(fmaxf(y1f, 0.f), 255.f);
            u32 ix0 = (u32)(int)fminf(fmaxf(x0f, 0.f), 255.f);
            u32 ix1 = (u32)(int)fminf(fmaxf(x1f, 0.f), 255.f);
            uint4 o;
            o.x = ((iy0 * WW + ix0) * CC) * 2u;
            o.y = ((iy0 * WW + ix1) * CC) * 2u;
            o.z = ((iy1 * WW + ix0) * CC) * 2u;
            o.w = ((iy1 * WW + ix1) * CC) * 2u;
            float4 cw = make_float4(wy0 * wx0 * vy0 * vx0, wy0 * wx1 * vy0 * vx1,
                                    wy1 * wx0 * vy1 * vx0, wy1 * wx1 * vy1 * vx1);
            *(uint4*) &sG[(buf * TPX + px) * 8]     = o;
            *(float4*)&sG[(buf * TPX + px) * 8 + 4] = cw;
        };

        setup(0, 0);
        BAR_SYNC(BAR_PROD, 128);

        for (int tap = 0; tap < NTAP; tap++) {
            int p = tap & 1;
            __half* sS16 = (__half*)sm + p * (TPX * 64);
            const float* gbase = &sG[(p * TPX + grp * 8) * 8];

            float4 cwb[2];
            uint4  da[2], db[2], dc[2], dd[2];
            {
                uint4 o0 = *(const uint4*)(gbase);
                cwb[0]   = *(const float4*)(gbase + 4);
                da[0] = __ldg((const uint4*)(xTb + o0.x) + f);
                db[0] = __ldg((const uint4*)(xTb + o0.y) + f);
                dc[0] = __ldg((const uint4*)(xTb + o0.z) + f);
                dd[0] = __ldg((const uint4*)(xTb + o0.w) + f);
                uint4 o1 = *(const uint4*)(gbase + 8);
                cwb[1]   = *(const float4*)(gbase + 12);
                da[1] = __ldg((const uint4*)(xTb + o1.x) + f);
                db[1] = __ldg((const uint4*)(xTb + o1.y) + f);
                dc[1] = __ldg((const uint4*)(xTb + o1.z) + f);
                dd[1] = __ldg((const uint4*)(xTb + o1.w) + f);
            }

            if (tap + 1 < NTAP) setup(tap + 1, 1 - p);

            if (tap >= 2) BAR_SYNC((p ? BAR_EMPTY1 : BAR_EMPTY0), 256);

            #pragma unroll
            for (int j = 0; j < 8; j++) {
                int sl = j & 1;
                float4 cw = cwb[sl];
                uint4 A = da[sl], B = db[sl], C = dc[sl], D = dd[sl];

                if (j < 6) {
                    uint4 on = *(const uint4*)(gbase + (j + 2) * 8);
                    cwb[sl]  = *(const float4*)(gbase + (j + 2) * 8 + 4);
                    da[sl] = __ldg((const uint4*)(xTb + on.x) + f);
                    db[sl] = __ldg((const uint4*)(xTb + on.y) + f);
                    dc[sl] = __ldg((const uint4*)(xTb + on.z) + f);
                    dd[sl] = __ldg((const uint4*)(xTb + on.w) + f);
                }

                // combine with packed fp32 FMA2 (bit-exact vs scalar FFMA)
                ull CW0, CW1, CW2, CW3, ZERO = 0ull;
                PACK2(CW0, cw.x, cw.x);
                PACK2(CW1, cw.y, cw.y);
                PACK2(CW2, cw.z, cw.z);
                PACK2(CW3, cw.w, cw.w);
                const __half2* ha = (const __half2*)&A;
                const __half2* hb = (const __half2*)&B;
                const __half2* hc = (const __half2*)&C;
                const __half2* hd = (const __half2*)&D;
                u32 outw[4];
                #pragma unroll
                for (int m = 0; m < 4; m++) {
                    float2 va = __half22float2(ha[m]);
                    float2 vb = __half22float2(hb[m]);
                    float2 vc = __half22float2(hc[m]);
                    float2 vd = __half22float2(hd[m]);
                    ull A2, B2, C2, D2, R;
                    PACK2(A2, va.x, va.y);
                    PACK2(B2, vb.x, vb.y);
                    PACK2(C2, vc.x, vc.y);
                    PACK2(D2, vd.x, vd.y);
                    FMA2(R, A2, CW0, ZERO);
                    FMA2(R, B2, CW1, R);
                    FMA2(R, C2, CW2, R);
                    FMA2(R, D2, CW3, R);
                    float r0, r1;
                    UNPACK2(r0, r1, R);
                    __half2 hr = __floats2half2_rn(r0, r1);
                    outw[m] = *(u32*)&hr;
                }
                // swizzled store: chunk f of pixel (grp*8+j) at position f^j
                *(uint4*)&sS16[(grp * 8 + j) * 64 + 8 * (f ^ j)] =
                    make_uint4(outw[0], outw[1], outw[2], outw[3]);
            }

            BAR_ARRIVE((p ? BAR_FULL1 : BAR_FULL0), 256);
            BAR_SYNC(BAR_PROD, 128);
        }
    } else {
        // ===================== CONSUMER (warps 4-7) ==========================
        int cwarp = wid - 4;
        int lg = lane >> 2;
        int le = lane & 3;
        int arow = cwarp * 32 + lg;

        float acc[2][8][4];
        #pragma unroll
        for (int mt = 0; mt < 2; mt++)
            #pragma unroll
            for (int nt = 0; nt < 8; nt++)
                #pragma unroll
                for (int e = 0; e < 4; e++) acc[mt][nt][e] = 0.f;

        for (int tap = 0; tap < NTAP; tap++) {
            int p = tap & 1;
            __half* sS16 = (__half*)sm + p * (TPX * 64);

            BAR_SYNC((p ? BAR_FULL1 : BAR_FULL0), 256);

            const uint2* wB = (const uint2*)g_weffH + (size_t)tap * 1024;
            #pragma unroll
            for (int s2 = 0; s2 < 4; s2++) {
                int sw = (((s2 << 1) + (le >> 1)) ^ lg) * 8 + (le & 1) * 4;
                uint2 a00 = *(const uint2*)&sS16[(arow)      * 64 + sw];
                uint2 a01 = *(const uint2*)&sS16[(arow + 8)  * 64 + sw];
                uint2 a10 = *(const uint2*)&sS16[(arow + 16) * 64 + sw];
                uint2 a11 = *(const uint2*)&sS16[(arow + 24) * 64 + sw];
                #pragma unroll
                for (int nt2 = 0; nt2 < 8; nt2++) {
                    int bidx = (((nt2 >> 2) * 4 + s2) * 4 + (nt2 & 3)) * 32 + lane;
                    uint2 bv = __ldg(wB + bidx);
                    mma_f16(acc[0][nt2], a00.x, a01.x, a00.y, a01.y, bv.x, bv.y);
                    mma_f16(acc[1][nt2], a10.x, a11.x, a10.y, a11.y, bv.x, bv.y);
                }
            }

            if (tap + 2 < NTAP)
                BAR_ARRIVE((p ? BAR_EMPTY1 : BAR_EMPTY0), 256);
        }

        BAR_SYNC(BAR_CONS, 128);

        float* sOut = sm;
        #pragma unroll
        for (int mt = 0; mt < 2; mt++) {
            int px0 = cwarp * 32 + mt * 16 + lg;
            #pragma unroll
            for (int nt2 = 0; nt2 < 8; nt2++) {
                int oo = (nt2 >> 2) * 32 + (nt2 & 3) * 8 + 2 * le;
                sOut[oo * TPX + px0]           = acc[mt][nt2][0];
                sOut[(oo + 1) * TPX + px0]     = acc[mt][nt2][1];
                sOut[oo * TPX + px0 + 8]       = acc[mt][nt2][2];
                sOut[(oo + 1) * TPX + px0 + 8] = acc[mt][nt2][3];
            }
        }
    }

    __syncthreads();
    {
        float* sOut = sm;
        int row = tid >> 2;
        int f0  = tid & 3;
        float4* op = (float4*)(out + (((size_t)(b * CC + row) * HH + h) * WW + w0));
        const float4* sp = (const float4*)(sOut + row * TPX);
        #pragma unroll
        for (int j = 0; j < 8; j++) op[f0 + j * 4] = sp[f0 + j * 4];
    }
}

// ---------------- launch ------------------------------------------------------
extern "C" void kernel_launch(void* const* d_in, const int* in_sizes, int n_in,
                              void* d_out, int out_size) {
    const float* x     = (const float*)d_in[0];
    const float* Woff  = (const float*)d_in[1];
    const float* boff  = (const float*)d_in[2];
    const float* Wd    = (const float*)d_in[3];
    const float* Wfuse = (const float*)d_in[4];
    float* out = (float*)d_out;

    int smem_main = SM_TOTAL;                 // 40960
    int smem_off  = 2 * 130 * 64 * 2;         // 33280 (>= 32768 epilogue)
    static int smem_set = 0;
    if (!smem_set) {
        cudaFuncSetAttribute(main_kernel,
                             cudaFuncAttributeMaxDynamicSharedMemorySize, smem_main);
        cudaFuncSetAttribute(offconv_kernel,
                             cudaFuncAttributeMaxDynamicSharedMemorySize, smem_off);
        smem_set = 1;
    }

    transpose_kernel<<<dim3(WW / 32, CC / 32, BB * HH), dim3(32, 8)>>>(x);
    weff_kernel<<<(ND * KK * CC * CC + 255) / 256, 256>>>(Wd, Wfuse);
    woff_kernel<<<(KK * CC * CC + 255) / 256, 256>>>(Woff);
    offconv_kernel<<<dim3(WW / TPX, BB * HH), 256, smem_off>>>(boff);
    main_kernel<<<dim3(WW / TPX, BB * HH), 256, smem_main>>>(out);
}

// round 15
// speedup vs baseline: 1.9954x; 1.0015x over previous
#include <cuda_runtime.h>
#include <cuda_fp16.h>
#include <cstdint>

#define BB   2
#define CC   64
#define HH   256
#define WW   256
#define KK   9
#define ND   3
#define NTAP 27
#define NOFF 54
#define TPX  128         // pixels per main-kernel block

typedef unsigned long long ull;
typedef unsigned int u32;

#define BAR_SYNC(id, cnt)   asm volatile("bar.sync %0, %1;"   :: "r"(id), "r"(cnt) : "memory")
#define BAR_ARRIVE(id, cnt) asm volatile("bar.arrive %0, %1;" :: "r"(id), "r"(cnt) : "memory")
// named barrier ids: FULL[i]=1+i, EMPTY[i]=4+i (i=0..2), consumer fence=7
#define BAR_FULL(i)  (1 + (i))
#define BAR_EMPTY(i) (4 + (i))
#define BAR_CONS     7

#define FMA2(d, a, b, c) asm("fma.rn.f32x2 %0, %1, %2, %3;" : "=l"(d) : "l"(a), "l"(b), "l"(c))
#define PACK2(d, lo, hi) asm("mov.b64 %0, {%1, %2};" : "=l"(d) : "f"(lo), "f"(hi))
#define UNPACK2(lo, hi, s) asm("mov.b64 {%0, %1}, %2;" : "=f"(lo), "=f"(hi) : "l"(s))

// m16n8k16 fp16 mma, fp32 accumulate (sm_80 baseline PTX -> HMMA on sm_103)
__device__ __forceinline__ void mma_f16(float* c,
                                        u32 a0, u32 a1, u32 a2, u32 a3,
                                        u32 b0, u32 b1) {
    asm("mma.sync.aligned.m16n8k16.row.col.f32.f16.f16.f32 "
        "{%0,%1,%2,%3}, {%4,%5,%6,%7}, {%8,%9}, {%0,%1,%2,%3};"
        : "+f"(c[0]), "+f"(c[1]), "+f"(c[2]), "+f"(c[3])
        : "r"(a0), "r"(a1), "r"(a2), "r"(a3), "r"(b0), "r"(b1));
}

// ---------------- scratch ----------------------------------------------------
__device__ __half g_xT[(size_t)BB * HH * WW * CC];         // fp16, P(c)-ordered NHWC
__device__ float  g_offT[(size_t)BB * HH * NOFF * WW];     // offsets (bh, ch, w)
__device__ __half g_weffH[(size_t)ND * KK * CC * CC];      // frag-ordered fp16
__device__ __half g_woffH[(size_t)KK * CC * CC];           // offset-conv weights

__device__ __forceinline__ int P_of(int c) {
    return (c >> 4) * 16 + ((c & 7) >> 1) * 4 + ((c >> 3) & 1) * 2 + (c & 1);
}
__device__ __forceinline__ int frag_index_h(int oo, int c) {
    int s = c >> 4, r = c & 15;
    int le = (r & 7) >> 1, hidx = ((r >> 3) << 1) | (r & 1);
    int wn = oo >> 5, nt = (oo >> 3) & 3, g = oo & 7;
    return ((((wn * 4 + s) * 4 + nt) * 32) + g * 4 + le) * 4 + hidx;
}

// ---------------- 1) transpose x -> fragment-ordered fp16 NHWC ----------------
__global__ void transpose_kernel(const float* __restrict__ x) {
    __shared__ float tile[32][33];
    int bh = blockIdx.z;
    int b  = bh / HH, h = bh % HH;
    int w0 = blockIdx.x * 32;
    int c0 = blockIdx.y * 32;
    int tx = threadIdx.x, ty = threadIdx.y;

    #pragma unroll
    for (int j = 0; j < 4; j++) {
        int c = c0 + ty + j * 8;
        tile[ty + j * 8][tx] = x[(((size_t)b * CC + c) * HH + h) * WW + (w0 + tx)];
    }
    __syncthreads();
    #pragma unroll
    for (int j = 0; j < 4; j++) {
        int w = w0 + ty + j * 8;
        int c = c0 + tx;
        g_xT[(((size_t)b * HH + h) * WW + w) * CC + P_of(c)] =
            __float2half(tile[tx][ty + j * 8]);
    }
}

// ---------------- 2a) Weff -> fragment-ordered fp16 ---------------------------
__global__ void weff_kernel(const float* __restrict__ Wd,
                            const float* __restrict__ Wfuse) {
    int idx = blockIdx.x * 256 + threadIdx.x;
    if (idx >= ND * KK * CC * CC) return;
    int oo = idx % CC;
    int c  = (idx / CC) % CC;
    int k  = (idx / (CC * CC)) % KK;
    int i  = idx / (CC * CC * KK);
    float acc = 0.f;
    #pragma unroll 8
    for (int o = 0; o < CC; o++) {
        acc = fmaf(Wfuse[oo * (ND * CC) + i * CC + o],
                   Wd[(((size_t)(i * CC + o) * CC + c) * KK) + k], acc);
    }
    int tap = i * KK + k;
    g_weffH[(size_t)tap * CC * CC + frag_index_h(oo, c)] = __float2half(acc);
}

// ---------------- 2b) Woff -> fragment-ordered fp16 ---------------------------
__global__ void woff_kernel(const float* __restrict__ Woff) {
    int idx = blockIdx.x * 256 + threadIdx.x;
    if (idx >= KK * CC * CC) return;
    int c  = idx % CC;
    int oc = (idx / CC) % CC;
    int k  = idx / (CC * CC);
    float v = (oc < NOFF) ? Woff[(size_t)oc * CC * KK + c * KK + k] : 0.f;
    g_woffH[(size_t)k * CC * CC + frag_index_h(oc, c)] = __float2half(v);
}

// ---------------- 3) offset conv via fp16 mma, swizzled smem -------------------
__global__ __launch_bounds__(256, 2)
void offconv_kernel(const float* __restrict__ boff) {
    extern __shared__ u32 smo[];
    __half* sX = (__half*)smo;

    int bh = blockIdx.y;
    int b  = bh / HH, h = bh % HH;
    int w0 = blockIdx.x * TPX;
    int tid = threadIdx.x;
    int lane = tid & 31, wid = tid >> 5;
    int warp_m = wid >> 1;
    int warp_n = wid & 1;
    int lg = lane >> 2;
    int le = lane & 3;

    const __half* xTrow = g_xT + (size_t)b * HH * WW * CC;

    float acc[2][4][4];
    #pragma unroll
    for (int mt = 0; mt < 2; mt++)
        #pragma unroll
        for (int nt = 0; nt < 4; nt++)
            #pragma unroll
            for (int e = 0; e < 4; e++) acc[mt][nt][e] = 0.f;

    for (int ky = 0; ky < 3; ky++) {
        int row = h + ky - 1;
        bool valid = (row >= 0 && row < HH);
        __half* sXp = sX + (ky & 1) * (130 * 64);

        if (valid) {
            const uint4* src = (const uint4*)(xTrow + (size_t)row * WW * CC);
            for (int t = tid; t < 130 * 8; t += 256) {
                int px = t >> 3, ch = t & 7;
                int w = w0 - 1 + px;
                uint4 val = make_uint4(0u, 0u, 0u, 0u);
                if (w >= 0 && w < WW) val = __ldg(src + (size_t)w * 8 + ch);
                *(uint4*)&sXp[px * 64 + 8 * (ch ^ (px & 7))] = val;
            }
        }
        __syncthreads();

        if (valid) {
            #pragma unroll
            for (int kx = 0; kx < 3; kx++) {
                int k = ky * 3 + kx;
                const uint2* wF2 = (const uint2*)g_woffH + (size_t)k * 1024 + warp_n * 512;
                int abase = warp_m * 32 + kx;
                int rs = (abase + lg) & 7;
                #pragma unroll
                for (int s2 = 0; s2 < 4; s2++) {
                    int sw = (((s2 << 1) + (le >> 1)) ^ rs) * 8 + (le & 1) * 4;
                    uint2 a00 = *(const uint2*)&sXp[(abase + lg)      * 64 + sw];
                    uint2 a01 = *(const uint2*)&sXp[(abase + lg + 8)  * 64 + sw];
                    uint2 a10 = *(const uint2*)&sXp[(abase + lg + 16) * 64 + sw];
                    uint2 a11 = *(const uint2*)&sXp[(abase + lg + 24) * 64 + sw];
                    #pragma unroll
                    for (int nt = 0; nt < 4; nt++) {
                        uint2 bv = __ldg(wF2 + (s2 * 4 + nt) * 32 + lane);
                        mma_f16(acc[0][nt], a00.x, a01.x, a00.y, a01.y, bv.x, bv.y);
                        mma_f16(acc[1][nt], a10.x, a11.x, a10.y, a11.y, bv.x, bv.y);
                    }
                }
            }
        }
    }

    float* sOut = (float*)smo;
    __syncthreads();
    #pragma unroll
    for (int mt = 0; mt < 2; mt++) {
        int px0 = warp_m * 32 + mt * 16 + lg;
        #pragma unroll
        for (int nt = 0; nt < 4; nt++) {
            int oc = warp_n * 32 + nt * 8 + 2 * le;
            float b0 = (oc < NOFF)     ? __ldg(&boff[oc])     : 0.f;
            float b1 = (oc + 1 < NOFF) ? __ldg(&boff[oc + 1]) : 0.f;
            sOut[oc * TPX + px0]           = acc[mt][nt][0] + b0;
            sOut[(oc + 1) * TPX + px0]     = acc[mt][nt][1] + b1;
            sOut[oc * TPX + px0 + 8]       = acc[mt][nt][2] + b0;
            sOut[(oc + 1) * TPX + px0 + 8] = acc[mt][nt][3] + b1;
        }
    }
    __syncthreads();
    {
        int oc = tid >> 2;
        int f0 = tid & 3;
        if (oc < NOFF) {
            float4* op = (float4*)(g_offT + ((size_t)bh * NOFF + oc) * WW + w0);
            const float4* sp = (const float4*)(sOut + oc * TPX);
            #pragma unroll
            for (int j = 0; j < 8; j++) op[f0 + j * 4] = sp[f0 + j * 4];
        }
    }
}

// ---------------- 4) main: warp-specialized, TRIPLE-buffered sS ----------------
// smem: sS 3*128*64 halves (49152B) + sG 2*128*8 floats (8192B) = 57344B
#define SMF_G   ((3 * TPX * 64 * 2) / 4)
#define SM_TOTAL (3 * TPX * 64 * 2 + 2 * TPX * 8 * 4)

__global__ __launch_bounds__(256, 2)
void main_kernel(float* __restrict__ out) {
    extern __shared__ float sm[];
    float* sG = sm + SMF_G;

    int bh = blockIdx.y;
    int b  = bh / HH, h = bh % HH;
    int w0 = blockIdx.x * TPX;
    int tid = threadIdx.x;
    int lane = tid & 31, wid = tid >> 5;

    const char*  xTb  = (const char*)(g_xT + (size_t)b * HH * WW * CC);
    const float* offb = g_offT + (size_t)bh * NOFF * WW + w0;

    if (tid < 128) {
        // ===================== PRODUCER (warps 0-3) ==========================
        int grp = tid >> 3;       // 16 groups, 8 px each
        int f   = tid & 7;        // 16B fp16 chunk lane

        auto setup = [&](int tap, int buf) {
            int px = tid;
            int i = tap / KK, k = tap - i * KK;
            int d = 1 << i;
            float dy = __ldg(offb + (size_t)(i * 18 + 2 * k) * WW + px);
            float dx = __ldg(offb + (size_t)(i * 18 + 2 * k + 1) * WW + px);
            float ys  = (float)h + (float)((k / 3 - 1) * d) + dy;
            float xsf = (float)(w0 + px) + (float)((k % 3 - 1) * d) + dx;
            float y0f = floorf(ys), x0f = floorf(xsf);
            float wy1 = ys - y0f, wx1 = xsf - x0f, wy0 = 1.f - wy1, wx0 = 1.f - wx1;
            float y1f = y0f + 1.f, x1f = x0f + 1.f;
            float vy0 = (y0f >= 0.f && y0f <= 255.f) ? 1.f : 0.f;
            float vy1 = (y1f >= 0.f && y1f <= 255.f) ? 1.f : 0.f;
            float vx0 = (x0f >= 0.f && x0f <= 255.f) ? 1.f : 0.f;
            float vx1 = (x1f >= 0.f && x1f <= 255.f) ? 1.f : 0.f;
            u32 iy0 = (u32)(int)fminf(fmaxf(y0f, 0.f), 255.f);
            u32 iy1 = (u32)(int)fminf(fmaxf(y1f, 0.f), 255.f);
            u32 ix0 = (u32)(int)fminf(fmaxf(x0f, 0.f), 255.f);
            u32 ix1 = (u32)(int)fminf(fmaxf(x1f, 0.f), 255.f);
            uint4 o;
            o.x = ((iy0 * WW + ix0) * CC) * 2u;
            o.y = ((iy0 * WW + ix1) * CC) * 2u;
            o.z = ((iy1 * WW + ix0) * CC) * 2u;
            o.w = ((iy1 * WW + ix1) * CC) * 2u;
            float4 cw = make_float4(wy0 * wx0 * vy0 * vx0, wy0 * wx1 * vy0 * vx1,
                                    wy1 * wx0 * vy1 * vx0, wy1 * wx1 * vy1 * vx1);
            *(uint4*) &sG[(buf * TPX + px) * 8]     = o;
            *(float4*)&sG[(buf * TPX + px) * 8 + 4] = cw;
        };

        setup(0, 0);
        __syncwarp();   // sG handoff is intra-8-thread-group -> warp sync suffices

        for (int tap = 0; tap < NTAP; tap++) {
            int ps = tap % 3;                 // sS buffer
            int pg = tap & 1;                 // sG buffer
            __half* sS16 = (__half*)sm + ps * (TPX * 64);
            const float* gbase = &sG[(pg * TPX + grp * 8) * 8];

            float4 cwb[2];
            uint4  da[2], db[2], dc[2], dd[2];
            {
                uint4 o0 = *(const uint4*)(gbase);
                cwb[0]   = *(const float4*)(gbase + 4);
                da[0] = __ldg((const uint4*)(xTb + o0.x) + f);
                db[0] = __ldg((const uint4*)(xTb + o0.y) + f);
                dc[0] = __ldg((const uint4*)(xTb + o0.z) + f);
                dd[0] = __ldg((const uint4*)(xTb + o0.w) + f);
                uint4 o1 = *(const uint4*)(gbase + 8);
                cwb[1]   = *(const float4*)(gbase + 12);
                da[1] = __ldg((const uint4*)(xTb + o1.x) + f);
                db[1] = __ldg((const uint4*)(xTb + o1.y) + f);
                dc[1] = __ldg((const uint4*)(xTb + o1.z) + f);
                dd[1] = __ldg((const uint4*)(xTb + o1.w) + f);
            }

            if (tap + 1 < NTAP) setup(tap + 1, 1 - pg);

            // wait for consumers to release this sS buffer (3 taps ago)
            if (tap >= 3) BAR_SYNC(BAR_EMPTY(ps), 256);

            #pragma unroll
            for (int j = 0; j < 8; j++) {
                int sl = j & 1;
                float4 cw = cwb[sl];
                uint4 A = da[sl], B = db[sl], C = dc[sl], D = dd[sl];

                if (j < 6) {
                    uint4 on = *(const uint4*)(gbase + (j + 2) * 8);
                    cwb[sl]  = *(const float4*)(gbase + (j + 2) * 8 + 4);
                    da[sl] = __ldg((const uint4*)(xTb + on.x) + f);
                    db[sl] = __ldg((const uint4*)(xTb + on.y) + f);
                    dc[sl] = __ldg((const uint4*)(xTb + on.z) + f);
                    dd[sl] = __ldg((const uint4*)(xTb + on.w) + f);
                }

                ull CW0, CW1, CW2, CW3, ZERO = 0ull;
                PACK2(CW0, cw.x, cw.x);
                PACK2(CW1, cw.y, cw.y);
                PACK2(CW2, cw.z, cw.z);
                PACK2(CW3, cw.w, cw.w);
                const __half2* ha = (const __half2*)&A;
                const __half2* hb = (const __half2*)&B;
                const __half2* hc = (const __half2*)&C;
                const __half2* hd = (const __half2*)&D;
                u32 outw[4];
                #pragma unroll
                for (int m = 0; m < 4; m++) {
                    float2 va = __half22float2(ha[m]);
                    float2 vb = __half22float2(hb[m]);
                    float2 vc = __half22float2(hc[m]);
                    float2 vd = __half22float2(hd[m]);
                    ull A2, B2, C2, D2, R;
                    PACK2(A2, va.x, va.y);
                    PACK2(B2, vb.x, vb.y);
                    PACK2(C2, vc.x, vc.y);
                    PACK2(D2, vd.x, vd.y);
                    FMA2(R, A2, CW0, ZERO);
                    FMA2(R, B2, CW1, R);
                    FMA2(R, C2, CW2, R);
                    FMA2(R, D2, CW3, R);
                    float r0, r1;
                    UNPACK2(r0, r1, R);
                    __half2 hr = __floats2half2_rn(r0, r1);
                    outw[m] = *(u32*)&hr;
                }
                *(uint4*)&sS16[(grp * 8 + j) * 64 + 8 * (f ^ j)] =
                    make_uint4(outw[0], outw[1], outw[2], outw[3]);
            }

            BAR_ARRIVE(BAR_FULL(ps), 256);
            __syncwarp();   // guards sG[1-pg] for next iteration (intra-group)
        }
    } else {
        // ===================== CONSUMER (warps 4-7) ==========================
        int cwarp = wid - 4;
        int lg = lane >> 2;
        int le = lane & 3;
        int arow = cwarp * 32 + lg;

        float acc[2][8][4];
        #pragma unroll
        for (int mt = 0; mt < 2; mt++)
            #pragma unroll
            for (int nt = 0; nt < 8; nt++)
                #pragma unroll
                for (int e = 0; e < 4; e++) acc[mt][nt][e] = 0.f;

        for (int tap = 0; tap < NTAP; tap++) {
            int ps = tap % 3;
            __half* sS16 = (__half*)sm + ps * (TPX * 64);

            BAR_SYNC(BAR_FULL(ps), 256);

            const uint2* wB = (const uint2*)g_weffH + (size_t)tap * 1024;
            #pragma unroll
            for (int s2 = 0; s2 < 4; s2++) {
                int sw = (((s2 << 1) + (le >> 1)) ^ lg) * 8 + (le & 1) * 4;
                uint2 a00 = *(const uint2*)&sS16[(arow)      * 64 + sw];
                uint2 a01 = *(const uint2*)&sS16[(arow + 8)  * 64 + sw];
                uint2 a10 = *(const uint2*)&sS16[(arow + 16) * 64 + sw];
                uint2 a11 = *(const uint2*)&sS16[(arow + 24) * 64 + sw];
                #pragma unroll
                for (int nt2 = 0; nt2 < 8; nt2++) {
                    int bidx = (((nt2 >> 2) * 4 + s2) * 4 + (nt2 & 3)) * 32 + lane;
                    uint2 bv = __ldg(wB + bidx);
                    mma_f16(acc[0][nt2], a00.x, a01.x, a00.y, a01.y, bv.x, bv.y);
                    mma_f16(acc[1][nt2], a10.x, a11.x, a10.y, a11.y, bv.x, bv.y);
                }
            }

            if (tap + 3 < NTAP)
                BAR_ARRIVE(BAR_EMPTY(ps), 256);
        }

        BAR_SYNC(BAR_CONS, 128);

        // sOut = sm[0..32KB) = sS buffers 0,1. Last producer writes hit buffer 2
        // (tap 26) and buffers 0,1 were consumed at taps 24,25 -> safe.
        float* sOut = sm;
        #pragma unroll
        for (int mt = 0; mt < 2; mt++) {
            int px0 = cwarp * 32 + mt * 16 + lg;
            #pragma unroll
            for (int nt2 = 0; nt2 < 8; nt2++) {
                int oo = (nt2 >> 2) * 32 + (nt2 & 3) * 8 + 2 * le;
                sOut[oo * TPX + px0]           = acc[mt][nt2][0];
                sOut[(oo + 1) * TPX + px0]     = acc[mt][nt2][1];
                sOut[oo * TPX + px0 + 8]       = acc[mt][nt2][2];
                sOut[(oo + 1) * TPX + px0 + 8] = acc[mt][nt2][3];
            }
        }
    }

    __syncthreads();
    {
        float* sOut = sm;
        int row = tid >> 2;
        int f0  = tid & 3;
        float4* op = (float4*)(out + (((size_t)(b * CC + row) * HH + h) * WW + w0));
        const float4* sp = (const float4*)(sOut + row * TPX);
        #pragma unroll
        for (int j = 0; j < 8; j++) op[f0 + j * 4] = sp[f0 + j * 4];
    }
}

// ---------------- launch ------------------------------------------------------
extern "C" void kernel_launch(void* const* d_in, const int* in_sizes, int n_in,
                              void* d_out, int out_size) {
    const float* x     = (const float*)d_in[0];
    const float* Woff  = (const float*)d_in[1];
    const float* boff  = (const float*)d_in[2];
    const float* Wd    = (const float*)d_in[3];
    const float* Wfuse = (const float*)d_in[4];
    float* out = (float*)d_out;

    int smem_main = SM_TOTAL;                 // 57344
    int smem_off  = 2 * 130 * 64 * 2;         // 33280
    static int smem_set = 0;
    if (!smem_set) {
        cudaFuncSetAttribute(main_kernel,
                             cudaFuncAttributeMaxDynamicSharedMemorySize, smem_main);
        cudaFuncSetAttribute(offconv_kernel,
                             cudaFuncAttributeMaxDynamicSharedMemorySize, smem_off);
        smem_set = 1;
    }

    transpose_kernel<<<dim3(WW / 32, CC / 32, BB * HH), dim3(32, 8)>>>(x);
    weff_kernel<<<(ND * KK * CC * CC + 255) / 256, 256>>>(Wd, Wfuse);
    woff_kernel<<<(KK * CC * CC + 255) / 256, 256>>>(Woff);
    offconv_kernel<<<dim3(WW / TPX, BB * HH), 256, smem_off>>>(boff);
    main_kernel<<<dim3(WW / TPX, BB * HH), 256, smem_main>>>(out);
}